// round 3
// baseline (speedup 1.0000x reference)
#include <cuda_runtime.h>
#include <cstdint>
#include <cstddef>

#define NB 256
#define NN 2048
#define NR 64
#define ND 64
#define NT 8
#define NPOS (NN - NR)
#define SLOTS 8
// smem floats: w1 16384 | w2 8192 | b1 128 | b2 64 | xT 1024 | hT 1024 | ints 64
#define OFF_W2 16384
#define OFF_B1 24576
#define OFF_B2 24704
#define OFF_XT 24768
#define OFF_HT 25792
#define OFF_IS 26816
#define SMEM_FLOATS 26880
#define SMEM_BYTES (SMEM_FLOATS * 4)

__device__ unsigned g_flag[NB * NN];
__device__ int g_list[NB * NPOS];
__device__ int g_ofs[NB * (NT + 1)];

static __device__ __forceinline__ unsigned ldacq(const unsigned* p) {
    unsigned v; asm volatile("ld.acquire.gpu.u32 %0,[%1];" : "=r"(v) : "l"(p) : "memory"); return v;
}
static __device__ __forceinline__ void strel(unsigned* p, unsigned v) {
    asm volatile("st.release.gpu.u32 [%0],%1;" :: "l"(p), "r"(v) : "memory");
}
static __device__ __forceinline__ void ffma2(unsigned long long& d, unsigned long long a, unsigned long long b) {
    asm("fma.rn.f32x2 %0,%1,%2,%0;" : "+l"(d) : "l"(a), "l"(b));
}
static __device__ __forceinline__ unsigned long long dup2(float x) {
    unsigned long long r; asm("mov.b64 %0,{%1,%1};" : "=l"(r) : "f"(x)); return r;
}
static __device__ __forceinline__ float2 unpk(unsigned long long v) {
    float2 f; asm("mov.b64 {%0,%1},%2;" : "=f"(f.x), "=f"(f.y) : "l"(v)); return f;
}
static __device__ __forceinline__ float gelu(float x) {
    return 0.5f * x * (1.0f + erff(x * 0.70710678118654752440f));
}

// ---------------- init: done-flags + copy root rows into out ----------------
__global__ void k_init(const float* __restrict__ root, float* __restrict__ out) {
    int tid = blockIdx.x * blockDim.x + threadIdx.x;
    int nt = gridDim.x * blockDim.x;
    for (int i = tid; i < NB * NN; i += nt)
        g_flag[i] = ((i & (NN - 1)) < NR) ? 1u : 0u;
    const float4* r4 = (const float4*)root;
    float4* o4 = (float4*)out;
    const int RD4 = NR * ND / 4;
    for (int i = tid; i < NB * RD4; i += nt) {
        int b = i / RD4;
        o4[(size_t)b * (NN * ND / 4) + (i - b * RD4)] = r4[i];
    }
}

// ---------------- per-batch, type-grouped, position-ordered task lists ------
__global__ void k_build(const int* __restrict__ types) {
    const int b = blockIdx.x, lane = threadIdx.x;
    const int* tb = types + b * NN + NR;
    int cnt[NT];
#pragma unroll
    for (int k = 0; k < NT; k++) cnt[k] = 0;
    for (int c = 0; c < NPOS; c += 32) {
        int v = tb[c + lane];
#pragma unroll
        for (int k = 0; k < NT; k++) cnt[k] += __popc(__ballot_sync(~0u, v == k));
    }
    int ofs[NT + 1];
    ofs[0] = 0;
#pragma unroll
    for (int k = 0; k < NT; k++) ofs[k + 1] = ofs[k] + cnt[k];
    if (lane <= NT) g_ofs[b * (NT + 1) + lane] = ofs[lane];
    int w[NT];
#pragma unroll
    for (int k = 0; k < NT; k++) w[k] = ofs[k];
    int* lst = g_list + b * NPOS;
    for (int c = 0; c < NPOS; c += 32) {
        int v = tb[c + lane], p = NR + c + lane;
#pragma unroll
        for (int k = 0; k < NT; k++) {
            unsigned m = __ballot_sync(~0u, v == k);
            if (v == k) lst[w[k] + __popc(m & ((1u << lane) - 1u))] = p;
            w[k] += __popc(m);
        }
    }
}

// ---------------- persistent type-specialized dataflow ----------------------
__global__ void __launch_bounds__(128, 2) k_main(
    const float* __restrict__ W1, const float* __restrict__ B1,
    const float* __restrict__ W2, const float* __restrict__ B2,
    const int* __restrict__ pidx, float* __restrict__ out)
{
    extern __shared__ float sm[];
    float* w1s = sm;
    float* w2s = sm + OFF_W2;
    float* b1s = sm + OFF_B1;
    float* b2s = sm + OFF_B2;
    float* xT  = sm + OFF_XT;   // [i=128][g=8]
    float* hT  = sm + OFF_HT;   // [j=128][g=8]
    int* ish  = (int*)(sm + OFF_IS);
    int* icur = ish;       int* iend = ish + 8;
    int* selp = ish + 16;  int* selb = ish + 24;
    int* sel1 = ish + 32;  int* sel2 = ish + 40;
    int* ctrl = ish + 48;  // [0]=Gr [1]=done

    const int t = threadIdx.x;
    const int ty = blockIdx.x >> 5;
    const int s = blockIdx.x & 31;

    { // weights -> smem (same layout, vector copy)
        const float4* a = (const float4*)(W1 + ty * 16384);
        for (int i = t; i < 4096; i += 128) ((float4*)w1s)[i] = a[i];
        const float4* c = (const float4*)(W2 + ty * 8192);
        for (int i = t; i < 2048; i += 128) ((float4*)w2s)[i] = c[i];
        b1s[t] = B1[ty * 128 + t];
        if (t < 64) b2s[t] = B2[ty * 64 + t];
        if (t < SLOTS) {
            int b = s + 32 * t;
            icur[t] = g_ofs[b * (NT + 1) + ty];
            iend[t] = g_ofs[b * (NT + 1) + ty + 1];
        }
    }
    __syncthreads();

    for (;;) {
        // Phase A: warp 0 harvests ready head tasks (non-blocking per slot)
        if (t < 32) {
            int pos = 0, bb = 0, p1 = 0, p2 = 0;
            long long tries = 0;
            for (;;) {
                int ok = 0, act = 0;
                if (t < SLOTS) {
                    int cu = icur[t];
                    if (cu < iend[t]) {
                        act = 1;
                        bb = s + 32 * t;
                        pos = g_list[bb * NPOS + cu];
                        int2 pp = *(const int2*)(pidx + ((size_t)bb * NN + pos) * 2);
                        p1 = pp.x; p2 = pp.y;
                        unsigned f1 = ldacq(&g_flag[bb * NN + p1]);
                        unsigned f2 = (p2 == p1) ? f1 : ldacq(&g_flag[bb * NN + p2]);
                        ok = (int)(f1 & f2);
                    }
                }
                unsigned mok = __ballot_sync(~0u, ok);
                unsigned mact = __ballot_sync(~0u, act);
                if (mok) {
                    if (ok) {
                        int r = __popc(mok & ((1u << t) - 1u));
                        selp[r] = pos; selb[r] = bb; sel1[r] = p1; sel2[r] = p2;
                        icur[t] = icur[t] + 1;
                    }
                    if (t == 0) { ctrl[0] = __popc(mok); ctrl[1] = 0; }
                    break;
                }
                if (!mact || ++tries > (4ll << 20)) {  // done (or safety bail: no hang)
                    if (t == 0) { ctrl[0] = 0; ctrl[1] = 1; }
                    break;
                }
                __nanosleep(64);
            }
        }
        __syncthreads();
        if (ctrl[1]) break;
        const int Gr = ctrl[0];

        // Phase B: gather parent features. thread t = input index i (0..127).
        {
            int half = (t >> 6);       // 0 -> parent0, 1 -> parent1
            int d = t & 63;
            for (int g = 0; g < Gr; g++) {
                int b = selb[g];
                int p = half ? sel2[g] : sel1[g];
                xT[t * 8 + g] = out[((size_t)b * NN + p) * ND + d];
            }
        }
        __syncthreads();

        // Phase C: hidden = GELU(x @ W1 + b1). thread t = hidden j.
        {
            unsigned long long acc0 = dup2(b1s[t]), acc1 = acc0, acc2 = acc0, acc3 = acc0;
#pragma unroll 8
            for (int i = 0; i < 128; i++) {
                unsigned long long w = dup2(w1s[i * 128 + t]);
                const unsigned long long* xr = (const unsigned long long*)(xT + i * 8);
                ffma2(acc0, xr[0], w);
                ffma2(acc1, xr[1], w);
                ffma2(acc2, xr[2], w);
                ffma2(acc3, xr[3], w);
            }
            float2 h01 = unpk(acc0), h23 = unpk(acc1), h45 = unpk(acc2), h67 = unpk(acc3);
            float hv[8] = {h01.x, h01.y, h23.x, h23.y, h45.x, h45.y, h67.x, h67.y};
            float* hr = hT + t * 8;
            for (int g = 0; g < Gr; g++) hr[g] = gelu(hv[g]);
        }
        __syncthreads();

        // Phase D: out = h @ W2 + b2, write rows. thread t: d = t&63, g-half = t>>6.
        {
            int d = t & 63, gh = t >> 6;
            unsigned long long a0 = dup2(b2s[d]), a1 = a0;
#pragma unroll 8
            for (int j = 0; j < 128; j++) {
                unsigned long long w = dup2(w2s[j * 64 + d]);
                const unsigned long long* hr = (const unsigned long long*)(hT + j * 8 + gh * 4);
                ffma2(a0, hr[0], w);
                ffma2(a1, hr[1], w);
            }
            float2 o01 = unpk(a0), o23 = unpk(a1);
            float ov[4] = {o01.x, o01.y, o23.x, o23.y};
            for (int gi = 0; gi < 4; gi++) {
                int g = gh * 4 + gi;
                if (g < Gr)
                    out[((size_t)selb[g] * NN + selp[g]) * ND + d] = ov[gi];
            }
        }
        __syncthreads();   // all row stores done (cumulative fence chain for release below)

        if (t < Gr)
            strel(&g_flag[selb[t] * NN + selp[t]], 1u);
    }
}

extern "C" void kernel_launch(void* const* d_in, const int* in_sizes, int n_in,
                              void* d_out, int out_size) {
    const float* root = (const float*)d_in[0];
    const float* W1   = (const float*)d_in[1];
    const float* b1   = (const float*)d_in[2];
    const float* W2   = (const float*)d_in[3];
    const float* b2   = (const float*)d_in[4];
    const int*   pidx = (const int*)d_in[5];
    const int*   typ  = (const int*)d_in[6];
    float* out = (float*)d_out;

    cudaFuncSetAttribute(k_main, cudaFuncAttributeMaxDynamicSharedMemorySize, SMEM_BYTES);
    k_init<<<256, 256>>>(root, out);
    k_build<<<NB, 32>>>(typ);
    k_main<<<256, 128, SMEM_BYTES>>>(W1, b1, W2, b2, pidx, out);
}

// round 5
// speedup vs baseline: 1.0792x; 1.0792x over previous
#include <cuda_runtime.h>
#include <cstdint>
#include <cstddef>

#define NB 256
#define NN 2048
#define NR 64
#define ND 64
#define NT 8
#define NPOS (NN - NR)
#define G 12                 // tasks per group
#define THREADS 160          // 128 compute + 32 scheduler

// smem floats: w1 16384 | xT 128*12 | hT 128*12 | then ints
#define OFF_XT 16384
#define OFF_HT (16384 + 128 * G)
#define FLOATS_TOTAL (16384 + 2 * 128 * G)
#define INTS_TOTAL 160
#define SMEM_BYTES (FLOATS_TOTAL * 4 + INTS_TOTAL * 4)
// int area layout: icur[0..7] iend[8..15] buf0@16 buf1@80 (stride 64) done@144
// buf: [0]=Gr  [1..12]=pos  [13..24]=batch  [25..36]=p1  [37..48]=p2

__device__ unsigned g_flag[NB * NN];
__device__ int g_list[NB * NPOS];
__device__ int g_ofs[NB * (NT + 1)];

typedef unsigned long long ull;

static __device__ __forceinline__ unsigned ldacq(const unsigned* p) {
    unsigned v; asm volatile("ld.acquire.gpu.u32 %0,[%1];" : "=r"(v) : "l"(p) : "memory"); return v;
}
static __device__ __forceinline__ void strel(unsigned* p, unsigned v) {
    asm volatile("st.release.gpu.u32 [%0],%1;" :: "l"(p), "r"(v) : "memory");
}
static __device__ __forceinline__ void ffma2(ull& d, ull a, ull b) {
    asm("fma.rn.f32x2 %0,%1,%2,%0;" : "+l"(d) : "l"(a), "l"(b));
}
static __device__ __forceinline__ ull dup2(float x) {
    ull r; asm("mov.b64 %0,{%1,%1};" : "=l"(r) : "f"(x)); return r;
}
static __device__ __forceinline__ float2 unpk(ull v) {
    float2 f; asm("mov.b64 {%0,%1},%2;" : "=f"(f.x), "=f"(f.y) : "l"(v)); return f;
}
static __device__ __forceinline__ float gelu(float x) {
    return 0.5f * x * (1.0f + erff(x * 0.70710678118654752440f));
}
static __device__ __forceinline__ void barc() {   // compute-warps-only barrier
    asm volatile("bar.sync 1, 128;" ::: "memory");
}

// ---------------- init: done-flags + copy root rows into out ----------------
__global__ void k_init(const float* __restrict__ root, float* __restrict__ out) {
    int tid = blockIdx.x * blockDim.x + threadIdx.x;
    int nt = gridDim.x * blockDim.x;
    for (int i = tid; i < NB * NN; i += nt)
        g_flag[i] = ((i & (NN - 1)) < NR) ? 1u : 0u;
    const float4* r4 = (const float4*)root;
    float4* o4 = (float4*)out;
    const int RD4 = NR * ND / 4;
    for (int i = tid; i < NB * RD4; i += nt) {
        int b = i / RD4;
        o4[(size_t)b * (NN * ND / 4) + (i - b * RD4)] = r4[i];
    }
}

// ---------------- per-batch, type-grouped, position-ordered task lists ------
__global__ void k_build(const int* __restrict__ types) {
    const int b = blockIdx.x, lane = threadIdx.x;
    const int* tb = types + b * NN + NR;
    int cnt[NT];
#pragma unroll
    for (int k = 0; k < NT; k++) cnt[k] = 0;
    for (int c = 0; c < NPOS; c += 32) {
        int v = tb[c + lane];
#pragma unroll
        for (int k = 0; k < NT; k++) cnt[k] += __popc(__ballot_sync(~0u, v == k));
    }
    int ofs[NT + 1];
    ofs[0] = 0;
#pragma unroll
    for (int k = 0; k < NT; k++) ofs[k + 1] = ofs[k] + cnt[k];
    if (lane <= NT) g_ofs[b * (NT + 1) + lane] = ofs[lane];
    int w[NT];
#pragma unroll
    for (int k = 0; k < NT; k++) w[k] = ofs[k];
    int* lst = g_list + b * NPOS;
    for (int c = 0; c < NPOS; c += 32) {
        int v = tb[c + lane], p = NR + c + lane;
#pragma unroll
        for (int k = 0; k < NT; k++) {
            unsigned m = __ballot_sync(~0u, v == k);
            if (v == k) lst[w[k] + __popc(m & ((1u << lane) - 1u))] = p;
            w[k] += __popc(m);
        }
    }
}

// ---------------- persistent type-specialized dataflow ----------------------
__global__ void __launch_bounds__(THREADS, 2) k_main(
    const float* __restrict__ W1, const float* __restrict__ B1,
    const float* __restrict__ W2, const float* __restrict__ B2,
    const int* __restrict__ pidx, float* __restrict__ out)
{
    extern __shared__ float sm[];
    float* w1s = sm;
    float* xT  = sm + OFF_XT;   // [i=128][g=12] row stride 48B (16B aligned)
    float* hT  = sm + OFF_HT;   // [j=128][g=12]
    int* ish = (int*)(sm + FLOATS_TOTAL);
    int* icur = ish;            // 8
    int* iend = ish + 8;        // 8

    const int t = threadIdx.x;
    const int ty = blockIdx.x >> 5;
    const int s = blockIdx.x & 31;

    // Preload W1 into smem; zero xT/hT; init cursors; register biases.
    {
        const float4* a = (const float4*)(W1 + ty * 16384);
        for (int i = t; i < 4096; i += THREADS) ((float4*)w1s)[i] = a[i];
        for (int i = t; i < 2 * 128 * G; i += THREADS) xT[i] = 0.0f;
        if (t < 8) {
            int b = s + 32 * t;
            icur[t] = g_ofs[b * (NT + 1) + ty];
            iend[t] = g_ofs[b * (NT + 1) + ty + 1];
        }
        if (t == 0) ish[144] = 0;
    }
    float rb1 = (t < 128) ? B1[ty * 128 + t] : 0.0f;
    float rb2 = (t < 128) ? B2[ty * 64 + (t & 63)] : 0.0f;
    const float* w2g = W2 + ty * 8192;
    __syncthreads();

    // ---- scheduler harvest (warp 4) into buffer nb: up to 2-deep per slot, cap G
    const int lane = t - 128;               // valid when t>=128
    const int slot = lane & 7, depth = lane >> 3;
    long long idle = 0;

#define HARVEST(nb)                                                            \
    {                                                                          \
        int retry = 0;                                                         \
        for (;;) {                                                             \
            int ok = 0, act = 0, pos = 0, bb = 0, p1 = 0, p2 = 0;              \
            if (lane < 16) {                                                   \
                int cu = icur[slot], ce = iend[slot];                          \
                act = (depth == 0) && (cu < ce);                               \
                int c2 = cu + depth;                                           \
                if (c2 < ce) {                                                 \
                    bb = s + 32 * slot;                                        \
                    pos = g_list[bb * NPOS + c2];                              \
                    int2 pp = *(const int2*)(pidx + ((size_t)bb * NN + pos) * 2); \
                    p1 = pp.x; p2 = pp.y;                                      \
                    unsigned f1 = ldacq(&g_flag[bb * NN + p1]);                \
                    unsigned f2 = (p2 == p1) ? f1 : ldacq(&g_flag[bb * NN + p2]); \
                    ok = (int)(f1 & f2);                                       \
                }                                                              \
            }                                                                  \
            unsigned m = __ballot_sync(~0u, ok);                               \
            int elig = ok && (depth == 0 || ((m >> slot) & 1));                \
            unsigned tm = __ballot_sync(~0u, elig);                            \
            int rank = __popc(tm & ((1u << lane) - 1u));                       \
            int take = elig && (rank < G);                                     \
            unsigned tk = __ballot_sync(~0u, take);                            \
            int cnt = __popc(tk);                                              \
            if (cnt) {                                                         \
                if (take) {                                                    \
                    (nb)[1 + rank] = pos; (nb)[13 + rank] = bb;                \
                    (nb)[25 + rank] = p1; (nb)[37 + rank] = p2;                \
                }                                                              \
                if (lane < 8) icur[lane] += ((tk >> lane) & 1) + ((tk >> (lane + 8)) & 1); \
                if (lane == 0) (nb)[0] = cnt;                                  \
                idle = 0;                                                      \
                break;                                                         \
            }                                                                  \
            unsigned am = __ballot_sync(~0u, act);                             \
            if (!am || idle > (1ll << 24)) {                                   \
                if (lane == 0) { (nb)[0] = 0; ish[144] = 1; }                  \
                break;                                                         \
            }                                                                  \
            if (++retry > 8) { if (lane == 0) (nb)[0] = 0; idle++; break; }    \
            __nanosleep(100);                                                  \
        }                                                                      \
    }

    // prologue: fill buffer 0
    if (t >= 128) HARVEST(ish + 16);

    int cur = 0;
    for (;;) {
        __syncthreads();
        int* cb = ish + 16 + 64 * cur;
        int Gr = cb[0];
        int dn = ish[144];
        if (Gr == 0 && dn) break;

        if (t >= 128) {
            if (!dn) HARVEST(ish + 16 + 64 * (cur ^ 1))
            else if (lane == 0) (ish + 16 + 64 * (cur ^ 1))[0] = 0;
        } else if (Gr > 0) {
            const int par = t >> 6, d = t & 63;
            // ---- Phase B: gather parent rows (coalesced LDG, STS.128)
            float xb[G];
#pragma unroll
            for (int r = 0; r < G; r++) {
                float v = 0.0f;
                if (r < Gr) {
                    int b = cb[13 + r];
                    int p = par ? cb[37 + r] : cb[25 + r];
                    v = out[((size_t)b * NN + p) * ND + d];
                }
                xb[r] = v;
            }
            {
                float4* xr = (float4*)(xT + (par * 64 + d) * G);
                xr[0] = make_float4(xb[0], xb[1], xb[2], xb[3]);
                xr[1] = make_float4(xb[4], xb[5], xb[6], xb[7]);
                xr[2] = make_float4(xb[8], xb[9], xb[10], xb[11]);
            }
            barc();

            // ---- Phase C: h[j=t][g] = GELU(x @ W1 + b1)
            {
                ull a0 = dup2(rb1), a1 = a0, a2 = a0, a3 = a0, a4 = a0, a5 = a0;
#pragma unroll 4
                for (int i = 0; i < 128; i++) {
                    ull w = dup2(w1s[i * 128 + t]);
                    const ulonglong2* xq = (const ulonglong2*)(xT + i * G);
                    ulonglong2 q0 = xq[0], q1 = xq[1], q2 = xq[2];
                    ffma2(a0, q0.x, w); ffma2(a1, q0.y, w);
                    ffma2(a2, q1.x, w); ffma2(a3, q1.y, w);
                    ffma2(a4, q2.x, w); ffma2(a5, q2.y, w);
                }
                float2 f0 = unpk(a0), f1 = unpk(a1), f2 = unpk(a2);
                float2 f3 = unpk(a3), f4 = unpk(a4), f5 = unpk(a5);
                float4* hr = (float4*)(hT + t * G);
                hr[0] = make_float4(gelu(f0.x), gelu(f0.y), gelu(f1.x), gelu(f1.y));
                hr[1] = make_float4(gelu(f2.x), gelu(f2.y), gelu(f3.x), gelu(f3.y));
                hr[2] = make_float4(gelu(f4.x), gelu(f4.y), gelu(f5.x), gelu(f5.y));
            }
            barc();

            // ---- Phase D: out = h @ W2 + b2 (w2 from global/L1, off the crossbar)
            {
                const int gh = par;        // g-range: gh*6 .. gh*6+5
                ull c0 = dup2(rb2), c1 = c0, c2 = c0;
#pragma unroll 4
                for (int j = 0; j < 128; j++) {
                    ull w = dup2(__ldg(w2g + j * 64 + d));
                    const ull* hq = (const ull*)(hT + j * G + gh * 6);
                    ffma2(c0, hq[0], w); ffma2(c1, hq[1], w); ffma2(c2, hq[2], w);
                }
                float2 o0 = unpk(c0), o1 = unpk(c1), o2 = unpk(c2);
                float ov[6] = {o0.x, o0.y, o1.x, o1.y, o2.x, o2.y};
#pragma unroll
                for (int k = 0; k < 6; k++) {
                    int g = gh * 6 + k;
                    if (g < Gr)
                        out[((size_t)cb[13 + g] * NN + cb[1 + g]) * ND + d] = ov[k];
                }
            }
            barc();   // all row stores complete before publishing

            if (t < Gr)
                strel(&g_flag[cb[13 + t] * NN + cb[1 + t]], 1u);
        }
        cur ^= 1;
    }
#undef HARVEST
}

extern "C" void kernel_launch(void* const* d_in, const int* in_sizes, int n_in,
                              void* d_out, int out_size) {
    const float* root = (const float*)d_in[0];
    const float* W1   = (const float*)d_in[1];
    const float* b1   = (const float*)d_in[2];
    const float* W2   = (const float*)d_in[3];
    const float* b2   = (const float*)d_in[4];
    const int*   pidx = (const int*)d_in[5];
    const int*   typ  = (const int*)d_in[6];
    float* out = (float*)d_out;

    cudaFuncSetAttribute(k_main, cudaFuncAttributeMaxDynamicSharedMemorySize, SMEM_BYTES);
    k_init<<<256, 256>>>(root, out);
    k_build<<<NB, 32>>>(typ);
    k_main<<<256, THREADS, SMEM_BYTES>>>(W1, b1, W2, b2, pidx, out);
}

// round 6
// speedup vs baseline: 1.1032x; 1.0223x over previous
#include <cuda_runtime.h>
#include <cstdint>
#include <cstddef>

#define NB 256
#define NN 2048
#define NR 64
#define ND 64
#define NT 8
#define G 16
#define THREADS 256
#define LM 510              // max level id supported
#define TASKCAP 2560
#define XS 20               // float stride of xT/hT rows (16B-aligned quads, conflict-reduced)

typedef unsigned long long ull;

__device__ unsigned short g_lvl[NB * NN];
__device__ int g_maxlvl;
__device__ unsigned g_arrive;
__device__ int g_tasks[256 * TASKCAP];       // pos | (u<<11)
__device__ int g_lofs[256 * (LM + 2)];

static __device__ __forceinline__ unsigned ldacq(const unsigned* p) {
    unsigned v; asm volatile("ld.acquire.gpu.u32 %0,[%1];" : "=r"(v) : "l"(p) : "memory"); return v;
}
static __device__ __forceinline__ void ffma2(ull& d, ull a, ull b) {
    asm("fma.rn.f32x2 %0,%1,%2,%0;" : "+l"(d) : "l"(a), "l"(b));
}
static __device__ __forceinline__ ull dup2(float x) {
    ull r; asm("mov.b64 %0,{%1,%1};" : "=l"(r) : "f"(x)); return r;
}
static __device__ __forceinline__ float2 unpk(ull v) {
    float2 f; asm("mov.b64 {%0,%1},%2;" : "=f"(f.x), "=f"(f.y) : "l"(v)); return f;
}
static __device__ __forceinline__ float gelu(float x) {
    return 0.5f * x * (1.0f + erff(x * 0.70710678118654752440f));
}

// -------- init: roots -> out, reset barrier/maxlvl ---------------------------
__global__ void k_init(const float* __restrict__ root, float* __restrict__ out) {
    int tid = blockIdx.x * blockDim.x + threadIdx.x;
    int nt = gridDim.x * blockDim.x;
    if (tid == 0) { g_arrive = 0u; g_maxlvl = 0; }
    const float4* r4 = (const float4*)root;
    float4* o4 = (float4*)out;
    const int RD4 = NR * ND / 4;
    for (int i = tid; i < NB * RD4; i += nt) {
        int b = i / RD4;
        o4[(size_t)b * (NN * ND / 4) + (i - b * RD4)] = r4[i];
    }
}

// -------- exact levels: one thread per batch, smem depth array --------------
__global__ void k_depth(const int* __restrict__ pidx) {
    extern __shared__ unsigned short slvl[];
    const int b = blockIdx.x * 32 + threadIdx.x;
    unsigned short* L = slvl + threadIdx.x * NN;
#pragma unroll
    for (int i = 0; i < NR; i++) L[i] = 0;
    const int2* pp = (const int2*)pidx + (size_t)b * NN;
    unsigned short* gl = g_lvl + (size_t)b * NN;
    int maxl = 0;
    for (int i = NR; i < NN; i += 2) {          // int4 covers 2 nodes' parents
        int4 q = *(const int4*)(pp + i);
        int l1 = L[q.x], l2 = L[q.y];
        int la = 1 + (l1 > l2 ? l1 : l2);
        L[i] = (unsigned short)la; gl[i] = (unsigned short)la;
        int l3 = L[q.z], l4 = L[q.w];
        int lb = 1 + (l3 > l4 ? l3 : l4);
        L[i + 1] = (unsigned short)lb; gl[i + 1] = (unsigned short)lb;
        int m = la > lb ? la : lb;
        if (m > maxl) maxl = m;
    }
    atomicMax(&g_maxlvl, maxl);
}

// -------- counting-sort per-CTA tasks by level ------------------------------
__global__ void k_build(const int* __restrict__ types) {
    __shared__ int cnt[LM + 2];
    __shared__ int wr[LM + 2];
    const int c = blockIdx.x, ty = c >> 5, s = c & 31, t = threadIdx.x;
    const int ml = g_maxlvl;
    for (int l = t; l < LM + 2; l += THREADS) cnt[l] = 0;
    __syncthreads();
    for (int u = 0; u < 8; u++) {
        const int b = s + 32 * u;
        for (int i = NR + t; i < NN; i += THREADS)
            if (types[b * NN + i] == ty)
                atomicAdd(&cnt[g_lvl[b * NN + i]], 1);
    }
    __syncthreads();
    if (t == 0) {
        int run = 0;
        for (int l = 1; l <= ml; l++) {
            int v = cnt[l];
            cnt[l] = run; wr[l] = run;
            run += v;
        }
        cnt[ml + 1] = run;
    }
    __syncthreads();
    for (int l = 1 + t; l <= ml + 1; l += THREADS)
        g_lofs[c * (LM + 2) + l] = cnt[l];
    for (int u = 0; u < 8; u++) {
        const int b = s + 32 * u;
        for (int i = NR + t; i < NN; i += THREADS)
            if (types[b * NN + i] == ty) {
                int idx = atomicAdd(&wr[g_lvl[b * NN + i]], 1);
                if (idx < TASKCAP) g_tasks[c * TASKCAP + idx] = i | (u << 11);
            }
    }
}

// -------- main: level-synchronous, type-specialized -------------------------
// smem: w1 16384 | xT 128*XS | hT 128*XS | rowb 32 | outb 16
#define OFF_XT 16384
#define OFF_HT (16384 + 128 * XS)
#define OFF_IS (16384 + 256 * XS)
#define SMEM_BYTES ((OFF_IS + 48) * 4)

__global__ void __launch_bounds__(THREADS, 2) k_main(
    const float* __restrict__ W1, const float* __restrict__ B1,
    const float* __restrict__ W2, const float* __restrict__ B2,
    const int* __restrict__ pidx, float* __restrict__ out)
{
    extern __shared__ float sm[];
    float* w1s = sm;
    float* xT = sm + OFF_XT;       // [i=128][XS] (g in first 16)
    float* hT = sm + OFF_HT;       // [j=128][XS]
    int* rowb = (int*)(sm + OFF_IS);   // 32: parent row bases
    int* outb = rowb + 32;             // 16: output row bases

    const int t = threadIdx.x, ty = blockIdx.x >> 5, s = blockIdx.x & 31;

    {
        const float4* a = (const float4*)(W1 + ty * 16384);
        for (int i = t; i < 4096; i += THREADS) ((float4*)w1s)[i] = a[i];
    }
    const float rb1 = B1[ty * 128 + (t & 127)];
    const float rb2 = B2[ty * 64 + (t & 63)];
    const float* w2g = W2 + ty * 8192;
    const int ml = g_maxlvl;
    const int* lofs = g_lofs + blockIdx.x * (LM + 2);
    const int* tasks = g_tasks + blockIdx.x * TASKCAP;
    __syncthreads();

    unsigned bar_target = 0;
    for (int l = 1; l <= ml; l++) {
        const int beg = lofs[l], end = lofs[l + 1];
        for (int k0 = beg; k0 < end; k0 += G) {
            const int Gr = min(G, end - k0);
            // setup: row bases for parents + outputs
            if (t < 2 * G) {
                int g = t >> 1, kk = t & 1;
                if (g < Gr) {
                    int task = tasks[k0 + g];
                    int pos = task & 2047, u = task >> 11;
                    int b = s + 32 * u;
                    int p = pidx[((size_t)b * NN + pos) * 2 + kk];
                    rowb[t] = (b * NN + p) * ND;
                    if (kk == 0) outb[g] = (b * NN + pos) * ND;
                }
            }
            __syncthreads();
            // gather -> xT[i][g]
            {
                int i = t & 127, gh = t >> 7;
                int d = i & 63, kk = i >> 6;
#pragma unroll
                for (int e = 0; e < 8; e++) {
                    int g = gh * 8 + e;
                    float v = 0.0f;
                    if (g < Gr) v = out[rowb[g * 2 + kk] + d];
                    xT[i * XS + g] = v;
                }
            }
            __syncthreads();
            // C: h[j][g] = gelu(x@W1 + b1); thread = (j = t&127, g-half = t>>7)
            {
                int j = t & 127, gh = t >> 7;
                ull a0 = dup2(rb1), a1 = a0, a2 = a0, a3 = a0;
#pragma unroll 8
                for (int i = 0; i < 128; i++) {
                    ull w = dup2(w1s[i * 128 + j]);
                    const ulonglong2* q = (const ulonglong2*)(xT + i * XS + gh * 8);
                    ulonglong2 q0 = q[0], q1 = q[1];
                    ffma2(a0, q0.x, w); ffma2(a1, q0.y, w);
                    ffma2(a2, q1.x, w); ffma2(a3, q1.y, w);
                }
                float2 f0 = unpk(a0), f1 = unpk(a1), f2 = unpk(a2), f3 = unpk(a3);
                float4* hr = (float4*)(hT + j * XS + gh * 8);
                hr[0] = make_float4(gelu(f0.x), gelu(f0.y), gelu(f1.x), gelu(f1.y));
                hr[1] = make_float4(gelu(f2.x), gelu(f2.y), gelu(f3.x), gelu(f3.y));
            }
            __syncthreads();
            // D: out[g][d] = h@W2 + b2; thread = (d = t&63, g-quad = t>>6); W2 via L1
            {
                int d = t & 63, gq = t >> 6;
                ull c0 = dup2(rb2), c1 = c0;
#pragma unroll 8
                for (int j = 0; j < 128; j++) {
                    ull w = dup2(__ldg(w2g + j * 64 + d));
                    ulonglong2 hq = *(const ulonglong2*)(hT + j * XS + gq * 4);
                    ffma2(c0, hq.x, w); ffma2(c1, hq.y, w);
                }
                float2 o0 = unpk(c0), o1 = unpk(c1);
                float ov[4] = {o0.x, o0.y, o1.x, o1.y};
#pragma unroll
                for (int e = 0; e < 4; e++) {
                    int g = gq * 4 + e;
                    if (g < Gr) out[outb[g] + d] = ov[e];
                }
            }
            __syncthreads();
        }
        // ---- grid barrier (all 256 CTAs wave-1 resident) ----
        bar_target += 256;
        if (t == 0) {
            __threadfence();                       // prior row stores visible
            atomicAdd(&g_arrive, 1u);
            long long spins = 0;
            while (ldacq(&g_arrive) < bar_target) {
                if (++spins > (1ll << 19)) break;  // safety bail (never in practice)
                __nanosleep(64);
            }
        }
        __syncthreads();
    }
}

extern "C" void kernel_launch(void* const* d_in, const int* in_sizes, int n_in,
                              void* d_out, int out_size) {
    const float* root = (const float*)d_in[0];
    const float* W1   = (const float*)d_in[1];
    const float* b1   = (const float*)d_in[2];
    const float* W2   = (const float*)d_in[3];
    const float* b2   = (const float*)d_in[4];
    const int*   pidx = (const int*)d_in[5];
    const int*   typ  = (const int*)d_in[6];
    float* out = (float*)d_out;

    cudaFuncSetAttribute(k_depth, cudaFuncAttributeMaxDynamicSharedMemorySize, 32 * NN * 2);
    cudaFuncSetAttribute(k_main, cudaFuncAttributeMaxDynamicSharedMemorySize, SMEM_BYTES);

    k_init<<<256, 256>>>(root, out);
    k_depth<<<8, 32, 32 * NN * 2>>>(pidx);
    k_build<<<256, THREADS>>>(typ);
    k_main<<<256, THREADS, SMEM_BYTES>>>(W1, b1, W2, b2, pidx, out);
}

// round 7
// speedup vs baseline: 1.1803x; 1.0699x over previous
#include <cuda_runtime.h>
#include <cstdint>
#include <cstddef>

#define NB 256
#define NN 2048
#define NR 64
#define ND 64
#define NT 8
#define G 32
#define THREADS 1024
#define LM 1022
#define TASKCAP 4608
#define XS 36                // float stride of xT/hT rows (16B aligned)

typedef unsigned long long ull;

__device__ unsigned short g_lvl[NB * NN];
__device__ int g_maxlvl;
__device__ unsigned g_arrive;
__device__ int g_tasks[128 * TASKCAP];    // pos | (u<<11), u<16
__device__ int g_lofs[128 * (LM + 2)];

static __device__ __forceinline__ unsigned ldacq(const unsigned* p) {
    unsigned v; asm volatile("ld.acquire.gpu.u32 %0,[%1];" : "=r"(v) : "l"(p) : "memory"); return v;
}
static __device__ __forceinline__ void ffma2(ull& d, ull a, ull b) {
    asm("fma.rn.f32x2 %0,%1,%2,%0;" : "+l"(d) : "l"(a), "l"(b));
}
static __device__ __forceinline__ ull add2(ull a, ull b) {
    ull r; asm("add.rn.f32x2 %0,%1,%2;" : "=l"(r) : "l"(a), "l"(b)); return r;
}
static __device__ __forceinline__ ull dup2(float x) {
    ull r; asm("mov.b64 %0,{%1,%1};" : "=l"(r) : "f"(x)); return r;
}
static __device__ __forceinline__ float2 unpk(ull v) {
    float2 f; asm("mov.b64 {%0,%1},%2;" : "=f"(f.x), "=f"(f.y) : "l"(v)); return f;
}
static __device__ __forceinline__ float gelu(float x) {
    return 0.5f * x * (1.0f + erff(x * 0.70710678118654752440f));
}

// -------- init: roots -> out, reset barrier/maxlvl --------------------------
__global__ void k_init(const float* __restrict__ root, float* __restrict__ out) {
    int tid = blockIdx.x * blockDim.x + threadIdx.x;
    int nt = gridDim.x * blockDim.x;
    if (tid == 0) { g_arrive = 0u; g_maxlvl = 0; }
    const float4* r4 = (const float4*)root;
    float4* o4 = (float4*)out;
    const int RD4 = NR * ND / 4;
    for (int i = tid; i < NB * RD4; i += nt) {
        int b = i / RD4;
        o4[(size_t)b * (NN * ND / 4) + (i - b * RD4)] = r4[i];
    }
}

// -------- exact longest-path levels: one thread per batch -------------------
__global__ void k_depth(const int* __restrict__ pidx) {
    extern __shared__ unsigned short slvl[];
    const int b = blockIdx.x * 32 + threadIdx.x;
    unsigned short* L = slvl + threadIdx.x * NN;
#pragma unroll
    for (int i = 0; i < NR; i++) L[i] = 0;
    const int2* pp = (const int2*)pidx + (size_t)b * NN;
    unsigned short* gl = g_lvl + (size_t)b * NN;
    int maxl = 0;
    for (int i = NR; i < NN; i += 2) {
        int4 q = *(const int4*)(pp + i);
        int l1 = L[q.x], l2 = L[q.y];
        int la = 1 + (l1 > l2 ? l1 : l2);
        L[i] = (unsigned short)la; gl[i] = (unsigned short)la;
        int l3 = L[q.z], l4 = L[q.w];
        int lb = 1 + (l3 > l4 ? l3 : l4);
        L[i + 1] = (unsigned short)lb; gl[i + 1] = (unsigned short)lb;
        int m = la > lb ? la : lb;
        if (m > maxl) maxl = m;
    }
    atomicMax(&g_maxlvl, maxl);
}

// -------- counting-sort per-CTA tasks by level (128 CTAs, 16 batches) -------
__global__ void k_build(const int* __restrict__ types) {
    __shared__ int cnt[LM + 2];
    __shared__ int wr[LM + 2];
    const int c = blockIdx.x, ty = c >> 4, s = c & 15, t = threadIdx.x;
    const int ml = g_maxlvl;
    for (int l = t; l < LM + 2; l += 256) cnt[l] = 0;
    __syncthreads();
    for (int u = 0; u < 16; u++) {
        const int b = s + 16 * u;
        for (int i = NR + t; i < NN; i += 256)
            if (types[b * NN + i] == ty)
                atomicAdd(&cnt[g_lvl[b * NN + i]], 1);
    }
    __syncthreads();
    if (t == 0) {
        int run = 0;
        for (int l = 1; l <= ml; l++) {
            int v = cnt[l];
            cnt[l] = run; wr[l] = run;
            run += v;
        }
        cnt[ml + 1] = run;
    }
    __syncthreads();
    for (int l = 1 + t; l <= ml + 1; l += 256)
        g_lofs[c * (LM + 2) + l] = cnt[l];
    for (int u = 0; u < 16; u++) {
        const int b = s + 16 * u;
        for (int i = NR + t; i < NN; i += 256)
            if (types[b * NN + i] == ty) {
                int idx = atomicAdd(&wr[g_lvl[b * NN + i]], 1);
                if (idx < TASKCAP) g_tasks[c * TASKCAP + idx] = i | (u << 11);
            }
    }
}

// -------- main: 1 CTA/SM, level-synchronous, split reductions ---------------
// smem floats: w1 16384 | w2 8192 | xT 128*36 | hT 128*36 | hP 128*36 | dP 64*9*4 | ints
#define OFF_W2 16384
#define OFF_XT 24576
#define OFF_HT (24576 + 128 * XS)
#define OFF_HP (OFF_HT + 128 * XS)
#define OFF_DP (OFF_HP + 128 * XS)
#define OFF_IS (OFF_DP + 64 * 9 * 4)
#define SMEM_BYTES ((OFF_IS + 128) * 4)

__global__ void __launch_bounds__(THREADS, 1) k_main(
    const float* __restrict__ W1, const float* __restrict__ B1,
    const float* __restrict__ W2, const float* __restrict__ B2,
    const int* __restrict__ pidx, float* __restrict__ out)
{
    extern __shared__ float sm[];
    float* w1s = sm;
    float* w2s = sm + OFF_W2;
    float* xT = sm + OFF_XT;       // [i=128][XS], g in first 32
    float* hT = sm + OFF_HT;       // [j=128][XS]
    float* hP = sm + OFF_HP;       // [j=128][gq*8..] partial h (padded rows of 36)
    float* dP = sm + OFF_DP;       // [d=64][gz] partial out, ull2 units stride 9
    int* rowb = (int*)(sm + OFF_IS);   // 64: parent row bases (g*2+kk)
    int* outb = rowb + 64;             // 32: output row bases

    const int t = threadIdx.x, ty = blockIdx.x >> 4, s = blockIdx.x & 15;

    {
        const float4* a = (const float4*)(W1 + ty * 16384);
        for (int i = t; i < 4096; i += THREADS) ((float4*)w1s)[i] = a[i];
        const float4* c2 = (const float4*)(W2 + ty * 8192);
        for (int i = t; i < 2048; i += THREADS) ((float4*)w2s)[i] = c2[i];
    }
    const float rb1 = B1[ty * 128 + (t & 127)];
    const float rb2 = B2[ty * 64 + (t & 63)];
    const int ml = g_maxlvl;
    const int* lofs = g_lofs + blockIdx.x * (LM + 2);
    const int* tasks = g_tasks + blockIdx.x * TASKCAP;
    __syncthreads();

    // phase-role constants
    const int jC = t & 127, gqC = (t >> 7) & 3, ihC = t >> 9;      // C: (j, 8g, i-half)
    const int dD = t & 63, gzD = (t >> 6) & 7, jhD = t >> 9;       // D: (d, 4g, j-half)
    const int dB = t & 63, rB = (t >> 6);                          // B: (d, row group)

    unsigned bar_target = 0;
    for (int l = 1; l <= ml; l++) {
        const int beg = lofs[l], end = lofs[l + 1];
        for (int k0 = beg; k0 < end; k0 += G) {
            const int Gr = min(G, end - k0);
            // ---- setup: row bases
            if (t < 2 * G) {
                int g = t >> 1, kk = t & 1;
                if (g < Gr) {
                    int task = tasks[k0 + g];
                    int pos = task & 2047, u = task >> 11;
                    int b = s + 16 * u;
                    int p = pidx[((size_t)b * NN + pos) * 2 + kk];
                    rowb[t] = (b * NN + p) * ND;
                    if (kk == 0) outb[g] = (b * NN + pos) * ND;
                }
            }
            __syncthreads();
            // ---- B: gather parents -> xT[i][g]
            {
#pragma unroll
                for (int e = 0; e < 4; e++) {
                    int r = rB + 16 * e;        // 0..63
                    int g = r >> 1, kk = r & 1;
                    float v = 0.0f;
                    if (g < Gr) v = out[rowb[r] + dB];
                    xT[(kk * 64 + dB) * XS + g] = v;
                }
            }
            __syncthreads();
            // ---- C: partial h over i-half; thread = (jC, 8 g at gqC*8, ihC)
            ull a0, a1, a2, a3;
            {
                ull bias = ihC ? 0ull : dup2(rb1);
                a0 = bias; a1 = bias; a2 = bias; a3 = bias;
                const int g0 = gqC * 8;
                const float* wp = w1s + (ihC * 64) * 128 + jC;
                const float* xp = xT + (ihC * 64) * XS + g0;
#pragma unroll 8
                for (int i = 0; i < 64; i++) {
                    ull w = dup2(wp[i * 128]);
                    const ulonglong2* q = (const ulonglong2*)(xp + i * XS);
                    ulonglong2 q0 = q[0], q1 = q[1];
                    ffma2(a0, q0.x, w); ffma2(a1, q0.y, w);
                    ffma2(a2, q1.x, w); ffma2(a3, q1.y, w);
                }
                if (ihC) {
                    float4* hp = (float4*)(hP + jC * XS + gqC * 8);
                    float2 f0 = unpk(a0), f1 = unpk(a1), f2 = unpk(a2), f3 = unpk(a3);
                    hp[0] = make_float4(f0.x, f0.y, f1.x, f1.y);
                    hp[1] = make_float4(f2.x, f2.y, f3.x, f3.y);
                }
            }
            __syncthreads();
            // ---- C-combine + GELU (ihC==0 threads)
            if (!ihC) {
                const ulonglong2* hp = (const ulonglong2*)(hP + jC * XS + gqC * 8);
                ulonglong2 p0 = hp[0], p1 = hp[1];
                float2 f0 = unpk(add2(a0, p0.x)), f1 = unpk(add2(a1, p0.y));
                float2 f2 = unpk(add2(a2, p1.x)), f3 = unpk(add2(a3, p1.y));
                float4* hr = (float4*)(hT + jC * XS + gqC * 8);
                hr[0] = make_float4(gelu(f0.x), gelu(f0.y), gelu(f1.x), gelu(f1.y));
                hr[1] = make_float4(gelu(f2.x), gelu(f2.y), gelu(f3.x), gelu(f3.y));
            }
            __syncthreads();
            // ---- D: partial out over j-half; thread = (dD, 4 g at gzD*4, jhD)
            ull c0, c1;
            {
                ull bias = jhD ? 0ull : dup2(rb2);
                c0 = bias; c1 = bias;
                const int g0 = gzD * 4;
                const float* wp = w2s + (jhD * 64) * 64 + dD;
                const float* hp = hT + (jhD * 64) * XS + g0;
#pragma unroll 8
                for (int j = 0; j < 64; j++) {
                    ull w = dup2(wp[j * 64]);
                    ulonglong2 hq = *(const ulonglong2*)(hp + j * XS);
                    ffma2(c0, hq.x, w); ffma2(c1, hq.y, w);
                }
                if (jhD) {
                    ulonglong2* dp = (ulonglong2*)(dP + (dD * 9 + gzD) * 4);
                    ulonglong2 v; v.x = c0; v.y = c1;
                    dp[0] = v;
                }
            }
            __syncthreads();
            // ---- D-combine + store rows (jhD==0 threads)
            if (!jhD) {
                ulonglong2 p = *(const ulonglong2*)(dP + (dD * 9 + gzD) * 4);
                float2 o0 = unpk(add2(c0, p.x)), o1 = unpk(add2(c1, p.y));
                float ov[4] = {o0.x, o0.y, o1.x, o1.y};
                const int g0 = gzD * 4;
#pragma unroll
                for (int e = 0; e < 4; e++) {
                    int g = g0 + e;
                    if (g < Gr) out[outb[g] + dD] = ov[e];
                }
            }
            __syncthreads();
        }
        // ---- grid barrier (128 CTAs, all resident at 1/SM)
        bar_target += 128;
        if (t == 0) {
            __threadfence();
            atomicAdd(&g_arrive, 1u);
            long long spins = 0;
            while (ldacq(&g_arrive) < bar_target) {
                if (++spins > (1ll << 20)) break;   // safety bail
                __nanosleep(32);
            }
        }
        __syncthreads();
    }
}

extern "C" void kernel_launch(void* const* d_in, const int* in_sizes, int n_in,
                              void* d_out, int out_size) {
    const float* root = (const float*)d_in[0];
    const float* W1   = (const float*)d_in[1];
    const float* b1   = (const float*)d_in[2];
    const float* W2   = (const float*)d_in[3];
    const float* b2   = (const float*)d_in[4];
    const int*   pidx = (const int*)d_in[5];
    const int*   typ  = (const int*)d_in[6];
    float* out = (float*)d_out;

    cudaFuncSetAttribute(k_depth, cudaFuncAttributeMaxDynamicSharedMemorySize, 32 * NN * 2);
    cudaFuncSetAttribute(k_main, cudaFuncAttributeMaxDynamicSharedMemorySize, SMEM_BYTES);

    k_init<<<256, 256>>>(root, out);
    k_depth<<<8, 32, 32 * NN * 2>>>(pidx);
    k_build<<<128, 256>>>(typ);
    k_main<<<128, THREADS, SMEM_BYTES>>>(W1, b1, W2, b2, pidx, out);
}

// round 9
// speedup vs baseline: 1.2466x; 1.0562x over previous
#include <cuda_runtime.h>
#include <cstdint>
#include <cstddef>

#define NB 256
#define NN 2048
#define NR 64
#define ND 64
#define NT 8
#define G 32
#define THREADS 1024
#define TCAP 81920
#define XS 36                // float stride of xT/hT rows

typedef unsigned long long ull;

__device__ unsigned short g_lvl[NB * NN];
__device__ int g_maxlvl;
__device__ unsigned g_arrive;
__device__ int g_cnt[128 * 1024];     // per (typeCTA slot, level) counts
__device__ int g_scat[128 * 1024];    // per (typeCTA slot, level) scatter base
__device__ int g_tlofs[NT * 1025];    // per type: level -> task offset (exclusive scan)
__device__ int g_curn[NT * 1024];     // per (type, level) steal cursor
__device__ int g_tasks[NT * TCAP];    // (b<<11)|pos, grouped by level per type

static __device__ __forceinline__ unsigned ldacq(const unsigned* p) {
    unsigned v; asm volatile("ld.acquire.gpu.u32 %0,[%1];" : "=r"(v) : "l"(p) : "memory"); return v;
}
static __device__ __forceinline__ void ffma2(ull& d, ull a, ull b) {
    asm("fma.rn.f32x2 %0,%1,%2,%0;" : "+l"(d) : "l"(a), "l"(b));
}
static __device__ __forceinline__ ull add2(ull a, ull b) {
    ull r; asm("add.rn.f32x2 %0,%1,%2;" : "=l"(r) : "l"(a), "l"(b)); return r;
}
static __device__ __forceinline__ ull dup2(float x) {
    ull r; asm("mov.b64 %0,{%1,%1};" : "=l"(r) : "f"(x)); return r;
}
static __device__ __forceinline__ float2 unpk(ull v) {
    float2 f; asm("mov.b64 {%0,%1},%2;" : "=f"(f.x), "=f"(f.y) : "l"(v)); return f;
}
static __device__ __forceinline__ float gelu(float x) {
    return 0.5f * x * (1.0f + erff(x * 0.70710678118654752440f));
}

// -------- init: roots -> out, reset barrier/maxlvl --------------------------
__global__ void k_init(const float* __restrict__ root, float* __restrict__ out) {
    int tid = blockIdx.x * blockDim.x + threadIdx.x;
    int nt = gridDim.x * blockDim.x;
    if (tid == 0) { g_arrive = 0u; g_maxlvl = 0; }
    const float4* r4 = (const float4*)root;
    float4* o4 = (float4*)out;
    const int RD4 = NR * ND / 4;
    for (int i = tid; i < NB * RD4; i += nt) {
        int b = i / RD4;
        o4[(size_t)b * (NN * ND / 4) + (i - b * RD4)] = r4[i];
    }
}

// -------- exact longest-path levels: one thread per batch -------------------
__global__ void k_depth(const int* __restrict__ pidx) {
    extern __shared__ unsigned short slvl[];
    const int b = blockIdx.x * 32 + threadIdx.x;
    unsigned short* L = slvl + threadIdx.x * NN;
#pragma unroll
    for (int i = 0; i < NR; i++) L[i] = 0;
    const int2* pp = (const int2*)pidx + (size_t)b * NN;
    unsigned short* gl = g_lvl + (size_t)b * NN;
    int maxl = 0;
    for (int i = NR; i < NN; i += 2) {
        int4 q = *(const int4*)(pp + i);
        int l1 = L[q.x], l2 = L[q.y];
        int la = 1 + (l1 > l2 ? l1 : l2);
        L[i] = (unsigned short)la; gl[i] = (unsigned short)la;
        int l3 = L[q.z], l4 = L[q.w];
        int lb = 1 + (l3 > l4 ? l3 : l4);
        L[i + 1] = (unsigned short)lb; gl[i + 1] = (unsigned short)lb;
        int m = la > lb ? la : lb;
        if (m > maxl) maxl = m;
    }
    atomicMax(&g_maxlvl, maxl);
}

// -------- count tasks per (slotCTA, level) ----------------------------------
__global__ void k_count(const int* __restrict__ types) {
    __shared__ int cnt[1024];
    const int c = blockIdx.x, ty = c >> 4, slot = c & 15, t = threadIdx.x;
    for (int l = t; l < 1024; l += 256) cnt[l] = 0;
    __syncthreads();
    for (int u = 0; u < 16; u++) {
        const int b = slot * 16 + u;
        for (int i = NR + t; i < NN; i += 256)
            if (types[b * NN + i] == ty)
                atomicAdd(&cnt[g_lvl[b * NN + i]], 1);
    }
    __syncthreads();
    for (int l = t; l < 1024; l += 256) g_cnt[c * 1024 + l] = cnt[l];
}

// -------- merge: per-type level offsets + per-slot scatter bases ------------
__global__ void k_merge() {
    __shared__ int sa[1024], sb_[1024];
    const int ty = blockIdx.x, l = threadIdx.x;     // 1024 threads = levels
    int cs[16]; int tot = 0;
#pragma unroll
    for (int s = 0; s < 16; s++) { cs[s] = g_cnt[(ty * 16 + s) * 1024 + l]; tot += cs[s]; }
    sa[l] = tot;
    __syncthreads();
    int* pin = sa; int* pout = sb_;
    for (int off = 1; off < 1024; off <<= 1) {
        int v = pin[l] + (l >= off ? pin[l - off] : 0);
        pout[l] = v;
        __syncthreads();
        int* tmp = pin; pin = pout; pout = tmp;
    }
    int incl = pin[l];
    int excl = incl - tot;
    g_tlofs[ty * 1025 + l] = excl;
    if (l == 1023) g_tlofs[ty * 1025 + 1024] = incl;
    int run = excl;
#pragma unroll
    for (int s = 0; s < 16; s++) { g_scat[(ty * 16 + s) * 1024 + l] = run; run += cs[s]; }
    g_curn[ty * 1024 + l] = 0;
}

// -------- scatter tasks into per-type level-grouped queue -------------------
__global__ void k_scatter(const int* __restrict__ types) {
    __shared__ int wr[1024];
    const int c = blockIdx.x, ty = c >> 4, slot = c & 15, t = threadIdx.x;
    for (int l = t; l < 1024; l += 256) wr[l] = g_scat[c * 1024 + l];
    __syncthreads();
    for (int u = 0; u < 16; u++) {
        const int b = slot * 16 + u;
        for (int i = NR + t; i < NN; i += 256)
            if (types[b * NN + i] == ty) {
                int idx = atomicAdd(&wr[g_lvl[b * NN + i]], 1);
                if (idx < TCAP) g_tasks[ty * TCAP + idx] = (b << 11) | i;
            }
    }
}

// -------- main: 1 CTA/SM, level-synchronous, work-stealing tiles ------------
// smem floats: w1 16384 | w2 8192 | xT 128*36 | hT 128*36 | hP 128*36 | dP 64*9*4 | ints
#define OFF_W2 16384
#define OFF_XT 24576
#define OFF_HT (24576 + 128 * XS)
#define OFF_HP (OFF_HT + 128 * XS)
#define OFF_DP (OFF_HP + 128 * XS)
#define OFF_IS (OFF_DP + 64 * 9 * 4)
#define SMEM_BYTES ((OFF_IS + 128) * 4)

__global__ void __launch_bounds__(THREADS, 1) k_main(
    const float* __restrict__ W1, const float* __restrict__ B1,
    const float* __restrict__ W2, const float* __restrict__ B2,
    const int* __restrict__ pidx, float* __restrict__ out)
{
    extern __shared__ float sm[];
    float* w1s = sm;
    float* w2s = sm + OFF_W2;
    float* xT = sm + OFF_XT;       // [i=128][XS], g in first 32
    float* hT = sm + OFF_HT;       // [j=128][XS]
    float* hP = sm + OFF_HP;       // partial h
    float* dP = sm + OFF_DP;       // partial out
    int* rowb = (int*)(sm + OFF_IS);   // 64: parent row bases (g*2+kk)
    int* outb = rowb + 64;             // 32: output row bases
    int* sgrab = outb + 32;            // 1: stolen tile base

    const int t = threadIdx.x, ty = blockIdx.x >> 4;

    {
        const float4* a = (const float4*)(W1 + ty * 16384);
        for (int i = t; i < 4096; i += THREADS) ((float4*)w1s)[i] = a[i];
        const float4* c2 = (const float4*)(W2 + ty * 8192);
        for (int i = t; i < 2048; i += THREADS) ((float4*)w2s)[i] = c2[i];
    }
    const float rb1 = B1[ty * 128 + (t & 127)];
    const float rb2 = B2[ty * 64 + (t & 63)];
    const int ml = g_maxlvl;
    const int* tlofs = g_tlofs + ty * 1025;
    const int* tasks = g_tasks + ty * TCAP;
    int* curs = g_curn + ty * 1024;
    __syncthreads();

    // phase-role constants
    const int jC = t & 127, gqC = (t >> 7) & 3, ihC = t >> 9;      // C: (j, 8g, i-half)
    const int dD = t & 63, gzD = (t >> 6) & 7, jhD = t >> 9;       // D: (d, 4g, j-half)
    const int dB = t & 63, rB = (t >> 6);                          // B: (d, row group)

    unsigned bar_target = 0;
    for (int l = 1; l <= ml; l++) {
        const int seg0 = tlofs[l], seg1 = tlofs[l + 1];
        for (;;) {
            if (t == 0) sgrab[0] = atomicAdd(&curs[l], G);
            __syncthreads();
            const int base = seg0 + sgrab[0];
            if (base >= seg1) break;
            const int Gr = min(G, seg1 - base);
            // ---- setup: row bases
            if (t < 2 * G) {
                int g = t >> 1, kk = t & 1;
                if (g < Gr) {
                    int task = tasks[base + g];
                    int pos = task & 2047, b = task >> 11;
                    int p = pidx[((size_t)b * NN + pos) * 2 + kk];
                    rowb[t] = (b * NN + p) * ND;
                    if (kk == 0) outb[g] = (b * NN + pos) * ND;
                }
            }
            __syncthreads();
            // ---- B: gather parents -> xT[i][g]
            {
#pragma unroll
                for (int e = 0; e < 4; e++) {
                    int r = rB + 16 * e;        // 0..63
                    int g = r >> 1, kk = r & 1;
                    float v = 0.0f;
                    if (g < Gr) v = out[rowb[r] + dB];
                    xT[(kk * 64 + dB) * XS + g] = v;
                }
            }
            __syncthreads();
            // ---- C: partial h over i-half; thread = (jC, 8 g at gqC*8, ihC)
            ull a0, a1, a2, a3;
            {
                ull bias = ihC ? 0ull : dup2(rb1);
                a0 = bias; a1 = bias; a2 = bias; a3 = bias;
                const int g0 = gqC * 8;
                const float* wp = w1s + (ihC * 64) * 128 + jC;
                const float* xp = xT + (ihC * 64) * XS + g0;
#pragma unroll 8
                for (int i = 0; i < 64; i++) {
                    ull w = dup2(wp[i * 128]);
                    const ulonglong2* q = (const ulonglong2*)(xp + i * XS);
                    ulonglong2 q0 = q[0], q1 = q[1];
                    ffma2(a0, q0.x, w); ffma2(a1, q0.y, w);
                    ffma2(a2, q1.x, w); ffma2(a3, q1.y, w);
                }
                if (ihC) {
                    float4* hp = (float4*)(hP + jC * XS + gqC * 8);
                    float2 f0 = unpk(a0), f1 = unpk(a1), f2 = unpk(a2), f3 = unpk(a3);
                    hp[0] = make_float4(f0.x, f0.y, f1.x, f1.y);
                    hp[1] = make_float4(f2.x, f2.y, f3.x, f3.y);
                }
            }
            __syncthreads();
            // ---- C-combine + GELU (ihC==0 threads)
            if (!ihC) {
                const ulonglong2* hp = (const ulonglong2*)(hP + jC * XS + gqC * 8);
                ulonglong2 p0 = hp[0], p1 = hp[1];
                float2 f0 = unpk(add2(a0, p0.x)), f1 = unpk(add2(a1, p0.y));
                float2 f2 = unpk(add2(a2, p1.x)), f3 = unpk(add2(a3, p1.y));
                float4* hr = (float4*)(hT + jC * XS + gqC * 8);
                hr[0] = make_float4(gelu(f0.x), gelu(f0.y), gelu(f1.x), gelu(f1.y));
                hr[1] = make_float4(gelu(f2.x), gelu(f2.y), gelu(f3.x), gelu(f3.y));
            }
            __syncthreads();
            // ---- D: partial out over j-half; thread = (dD, 4 g at gzD*4, jhD)
            ull c0, c1;
            {
                ull bias = jhD ? 0ull : dup2(rb2);
                c0 = bias; c1 = bias;
                const int g0 = gzD * 4;
                const float* wp = w2s + (jhD * 64) * 64 + dD;
                const float* hp = hT + (jhD * 64) * XS + g0;
#pragma unroll 8
                for (int j = 0; j < 64; j++) {
                    ull w = dup2(wp[j * 64]);
                    ulonglong2 hq = *(const ulonglong2*)(hp + j * XS);
                    ffma2(c0, hq.x, w); ffma2(c1, hq.y, w);
                }
                if (jhD) {
                    ulonglong2* dp = (ulonglong2*)(dP + (dD * 9 + gzD) * 4);
                    ulonglong2 v; v.x = c0; v.y = c1;
                    dp[0] = v;
                }
            }
            __syncthreads();
            // ---- D-combine + store rows (jhD==0 threads)
            if (!jhD) {
                ulonglong2 p = *(const ulonglong2*)(dP + (dD * 9 + gzD) * 4);
                float2 o0 = unpk(add2(c0, p.x)), o1 = unpk(add2(c1, p.y));
                float ov[4] = {o0.x, o0.y, o1.x, o1.y};
                const int g0 = gzD * 4;
#pragma unroll
                for (int e = 0; e < 4; e++) {
                    int g = g0 + e;
                    if (g < Gr) out[outb[g] + dD] = ov[e];
                }
            }
            __syncthreads();
        }
        // ---- grid barrier (128 CTAs, all resident at 1/SM)
        bar_target += 128;
        if (t == 0) {
            __threadfence();
            atomicAdd(&g_arrive, 1u);
            long long spins = 0;
            while (ldacq(&g_arrive) < bar_target) {
                if (++spins > (1ll << 20)) break;   // safety bail
                __nanosleep(32);
            }
        }
        __syncthreads();
    }
}

extern "C" void kernel_launch(void* const* d_in, const int* in_sizes, int n_in,
                              void* d_out, int out_size) {
    const float* root = (const float*)d_in[0];
    const float* W1   = (const float*)d_in[1];
    const float* b1   = (const float*)d_in[2];
    const float* W2   = (const float*)d_in[3];
    const float* b2   = (const float*)d_in[4];
    const int*   pidx = (const int*)d_in[5];
    const int*   typ  = (const int*)d_in[6];
    float* out = (float*)d_out;

    cudaFuncSetAttribute(k_depth, cudaFuncAttributeMaxDynamicSharedMemorySize, 32 * NN * 2);
    cudaFuncSetAttribute(k_main, cudaFuncAttributeMaxDynamicSharedMemorySize, SMEM_BYTES);

    k_init<<<256, 256>>>(root, out);
    k_depth<<<8, 32, 32 * NN * 2>>>(pidx);
    k_count<<<128, 256>>>(typ);
    k_merge<<<8, 1024>>>();
    k_scatter<<<128, 256>>>(typ);
    k_main<<<128, THREADS, SMEM_BYTES>>>(W1, b1, W2, b2, pidx, out);
}

// round 10
// speedup vs baseline: 1.3138x; 1.0539x over previous
#include <cuda_runtime.h>
#include <cstdint>
#include <cstddef>

#define NB 256
#define NN 2048
#define NR 64
#define ND 64
#define NT 8
#define G 64
#define THREADS 1024
#define TCAP 81920
#define XST 68               // xT/hT row stride in floats (272B: 16B aligned, conflict-free)

typedef unsigned long long ull;

__device__ unsigned short g_lvl[NB * NN];
__device__ int g_maxlvl;
__device__ unsigned g_arrive;
__device__ int g_cnt[128 * 1024];
__device__ int g_scat[128 * 1024];
__device__ int g_tlofs[NT * 1025];
__device__ int g_curn[NT * 1024];
__device__ int g_tasks[NT * TCAP];    // (b<<11)|pos, level-grouped per type

static __device__ __forceinline__ unsigned ldacq(const unsigned* p) {
    unsigned v; asm volatile("ld.acquire.gpu.u32 %0,[%1];" : "=r"(v) : "l"(p) : "memory"); return v;
}
static __device__ __forceinline__ void ffma2(ull& d, ull a, ull b) {
    asm("fma.rn.f32x2 %0,%1,%2,%0;" : "+l"(d) : "l"(a), "l"(b));
}
static __device__ __forceinline__ ull add2(ull a, ull b) {
    ull r; asm("add.rn.f32x2 %0,%1,%2;" : "=l"(r) : "l"(a), "l"(b)); return r;
}
static __device__ __forceinline__ ull dup2(float x) {
    ull r; asm("mov.b64 %0,{%1,%1};" : "=l"(r) : "f"(x)); return r;
}
static __device__ __forceinline__ float2 unpk(ull v) {
    float2 f; asm("mov.b64 {%0,%1},%2;" : "=f"(f.x), "=f"(f.y) : "l"(v)); return f;
}
static __device__ __forceinline__ float gelu(float x) {
    return 0.5f * x * (1.0f + erff(x * 0.70710678118654752440f));
}

// -------- init -------------------------------------------------------------
__global__ void k_init(const float* __restrict__ root, float* __restrict__ out) {
    int tid = blockIdx.x * blockDim.x + threadIdx.x;
    int nt = gridDim.x * blockDim.x;
    if (tid == 0) { g_arrive = 0u; g_maxlvl = 0; }
    const float4* r4 = (const float4*)root;
    float4* o4 = (float4*)out;
    const int RD4 = NR * ND / 4;
    for (int i = tid; i < NB * RD4; i += nt) {
        int b = i / RD4;
        o4[(size_t)b * (NN * ND / 4) + (i - b * RD4)] = r4[i];
    }
}

// -------- exact longest-path levels ----------------------------------------
__global__ void k_depth(const int* __restrict__ pidx) {
    extern __shared__ unsigned short slvl[];
    const int b = blockIdx.x * 32 + threadIdx.x;
    unsigned short* L = slvl + threadIdx.x * NN;
#pragma unroll
    for (int i = 0; i < NR; i++) L[i] = 0;
    const int2* pp = (const int2*)pidx + (size_t)b * NN;
    unsigned short* gl = g_lvl + (size_t)b * NN;
    int maxl = 0;
    for (int i = NR; i < NN; i += 2) {
        int4 q = *(const int4*)(pp + i);
        int l1 = L[q.x], l2 = L[q.y];
        int la = 1 + (l1 > l2 ? l1 : l2);
        L[i] = (unsigned short)la; gl[i] = (unsigned short)la;
        int l3 = L[q.z], l4 = L[q.w];
        int lb = 1 + (l3 > l4 ? l3 : l4);
        L[i + 1] = (unsigned short)lb; gl[i + 1] = (unsigned short)lb;
        int m = la > lb ? la : lb;
        if (m > maxl) maxl = m;
    }
    atomicMax(&g_maxlvl, maxl);
}

// -------- count / merge / scatter (per-type level queues) -------------------
__global__ void k_count(const int* __restrict__ types) {
    __shared__ int cnt[1024];
    const int c = blockIdx.x, ty = c >> 4, slot = c & 15, t = threadIdx.x;
    for (int l = t; l < 1024; l += 256) cnt[l] = 0;
    __syncthreads();
    for (int u = 0; u < 16; u++) {
        const int b = slot * 16 + u;
        for (int i = NR + t; i < NN; i += 256)
            if (types[b * NN + i] == ty)
                atomicAdd(&cnt[g_lvl[b * NN + i]], 1);
    }
    __syncthreads();
    for (int l = t; l < 1024; l += 256) g_cnt[c * 1024 + l] = cnt[l];
}

__global__ void k_merge() {
    __shared__ int sa[1024], sb_[1024];
    const int ty = blockIdx.x, l = threadIdx.x;
    int cs[16]; int tot = 0;
#pragma unroll
    for (int s = 0; s < 16; s++) { cs[s] = g_cnt[(ty * 16 + s) * 1024 + l]; tot += cs[s]; }
    sa[l] = tot;
    __syncthreads();
    int* pin = sa; int* pout = sb_;
    for (int off = 1; off < 1024; off <<= 1) {
        int v = pin[l] + (l >= off ? pin[l - off] : 0);
        pout[l] = v;
        __syncthreads();
        int* tmp = pin; pin = pout; pout = tmp;
    }
    int incl = pin[l];
    int excl = incl - tot;
    g_tlofs[ty * 1025 + l] = excl;
    if (l == 1023) g_tlofs[ty * 1025 + 1024] = incl;
    int run = excl;
#pragma unroll
    for (int s = 0; s < 16; s++) { g_scat[(ty * 16 + s) * 1024 + l] = run; run += cs[s]; }
    g_curn[ty * 1024 + l] = 0;
}

__global__ void k_scatter(const int* __restrict__ types) {
    __shared__ int wr[1024];
    const int c = blockIdx.x, ty = c >> 4, slot = c & 15, t = threadIdx.x;
    for (int l = t; l < 1024; l += 256) wr[l] = g_scat[c * 1024 + l];
    __syncthreads();
    for (int u = 0; u < 16; u++) {
        const int b = slot * 16 + u;
        for (int i = NR + t; i < NN; i += 256)
            if (types[b * NN + i] == ty) {
                int idx = atomicAdd(&wr[g_lvl[b * NN + i]], 1);
                if (idx < TCAP) g_tasks[ty * TCAP + idx] = (b << 11) | i;
            }
    }
}

// -------- main: G=64, 2D register blocking, work-stealing, 1 CTA/SM ---------
// smem floats:
#define OFF_W2 16384
#define OFF_XT 24576                     // [i=128][XST]
#define OFF_HT (OFF_XT + 128 * XST)      // [j=128][XST]
#define OFF_HP (OFF_HT + 128 * XST)      // 4096 ull partials (C)
#define OFF_DP (OFF_HP + 8192)           // 2048 ull partials (D)
#define OFF_B1 (OFF_DP + 4096)
#define OFF_B2 (OFF_B1 + 128)
#define OFF_IS (OFF_B2 + 64)
#define SMEM_BYTES ((OFF_IS + 200) * 4)

__global__ void __launch_bounds__(THREADS, 1) k_main(
    const float* __restrict__ W1, const float* __restrict__ B1,
    const float* __restrict__ W2, const float* __restrict__ B2,
    const int* __restrict__ pidx, float* __restrict__ out)
{
    extern __shared__ float sm[];
    float* w1s = sm;                   // [i=128][j=128]
    float* w2s = sm + OFF_W2;          // [j=128][d=64]
    float* xT  = sm + OFF_XT;
    float* hT  = sm + OFF_HT;
    ull*   hP  = (ull*)(sm + OFF_HP);  // [acc=8][thr=512]
    ull*   dP  = (ull*)(sm + OFF_DP);  // [acc=4][thr=512]
    float* b1s = sm + OFF_B1;
    float* b2s = sm + OFF_B2;
    int* rowb  = (int*)(sm + OFF_IS);  // 128
    int* outb  = rowb + 128;           // 64
    int* sgrab = outb + 64;            // 1

    const int t = threadIdx.x, w = t >> 5, lane = t & 31;
    const int ty = blockIdx.x >> 4;

    {
        const float4* a = (const float4*)(W1 + ty * 16384);
        for (int i = t; i < 4096; i += THREADS) ((float4*)w1s)[i] = a[i];
        const float4* c2 = (const float4*)(W2 + ty * 8192);
        for (int i = t; i < 2048; i += THREADS) ((float4*)w2s)[i] = c2[i];
        if (t < 128) b1s[t] = B1[ty * 128 + t];
        if (t < 64) b2s[t] = B2[ty * 64 + t];
    }
    const int ml = g_maxlvl;
    const int* tlofs = g_tlofs + ty * 1025;
    const int* tasks = g_tasks + ty * TCAP;
    int* curs = g_curn + ty * 1024;
    __syncthreads();

    // role constants
    const int wl = w & 15;
    // C: warp tile 16j x 32g, i-split 2
    const int ihC = w >> 4;
    const int j0C = (wl >> 1) * 16 + (lane >> 2) * 2;
    const int g0C = (wl & 1) * 32 + (lane & 3) * 8;
    const float bC0 = b1s[j0C], bC1 = b1s[j0C + 1];
    // D: warp tile 16d x 16g, j-split 2; accs paired over (d,d+1)
    const int jhD = w >> 4;
    const int d0D = (wl >> 2) * 16 + (lane >> 2) * 2;
    const int g0D = (wl & 3) * 16 + (lane & 3) * 4;
    const ull bD = *(const ull*)(b2s + d0D);
    // gather roles
    const int dB = t & 63, rB = t >> 6;

    unsigned bar_target = 0;
    for (int l = 1; l <= ml; l++) {
        const int seg0 = tlofs[l], seg1 = tlofs[l + 1];
        for (;;) {
            if (t == 0) sgrab[0] = atomicAdd(&curs[l], G);
            __syncthreads();
            const int base = seg0 + sgrab[0];
            if (base >= seg1) break;
            const int Gr = min(G, seg1 - base);

            // ---- setup row bases
            if (t < 2 * G) {
                int g = t >> 1, kk = t & 1;
                if (g < Gr) {
                    int task = tasks[base + g];
                    int pos = task & 2047, b = task >> 11;
                    int p = pidx[((size_t)b * NN + pos) * 2 + kk];
                    rowb[t] = (b * NN + p) * ND;
                    if (kk == 0) outb[g] = (b * NN + pos) * ND;
                }
            }
            __syncthreads();

            // ---- gather: 128 parent rows -> xT[i][g]
#pragma unroll
            for (int e = 0; e < 8; e++) {
                int r = rB + 16 * e;            // 0..127
                int g = r >> 1, kk = r & 1;
                float v = 0.0f;
                if (g < Gr) v = out[rowb[r] + dB];
                xT[(kk * 64 + dB) * XST + g] = v;
            }
            __syncthreads();

            // ---- C: h = gelu(x@W1+b1); thread: 2j x 8g, half-i
            {
                ull a0, a1, a2, a3, a4, a5, a6, a7;
                if (ihC) { a0 = a1 = a2 = a3 = a4 = a5 = a6 = a7 = 0ull; }
                else {
                    a0 = a1 = a2 = a3 = dup2(bC0);
                    a4 = a5 = a6 = a7 = dup2(bC1);
                }
                const float* wp = w1s + ihC * 64 * 128 + j0C;
                const float* xp = xT + ihC * 64 * XST + g0C;
#pragma unroll 8
                for (int i = 0; i < 64; i++) {
                    float2 wv = *(const float2*)(wp + i * 128);
                    ulonglong2 x01 = *(const ulonglong2*)(xp + i * XST);
                    ulonglong2 x23 = *(const ulonglong2*)(xp + i * XST + 4);
                    ull wa = dup2(wv.x), wb = dup2(wv.y);
                    ffma2(a0, x01.x, wa); ffma2(a1, x01.y, wa);
                    ffma2(a2, x23.x, wa); ffma2(a3, x23.y, wa);
                    ffma2(a4, x01.x, wb); ffma2(a5, x01.y, wb);
                    ffma2(a6, x23.x, wb); ffma2(a7, x23.y, wb);
                }
                const int p512 = wl * 32 + lane;
                if (ihC) {
                    hP[0 * 512 + p512] = a0; hP[1 * 512 + p512] = a1;
                    hP[2 * 512 + p512] = a2; hP[3 * 512 + p512] = a3;
                    hP[4 * 512 + p512] = a4; hP[5 * 512 + p512] = a5;
                    hP[6 * 512 + p512] = a6; hP[7 * 512 + p512] = a7;
                }
                __syncthreads();
                if (!ihC) {
                    a0 = add2(a0, hP[0 * 512 + p512]); a1 = add2(a1, hP[1 * 512 + p512]);
                    a2 = add2(a2, hP[2 * 512 + p512]); a3 = add2(a3, hP[3 * 512 + p512]);
                    a4 = add2(a4, hP[4 * 512 + p512]); a5 = add2(a5, hP[5 * 512 + p512]);
                    a6 = add2(a6, hP[6 * 512 + p512]); a7 = add2(a7, hP[7 * 512 + p512]);
                    float2 f0 = unpk(a0), f1 = unpk(a1), f2 = unpk(a2), f3 = unpk(a3);
                    float4* hr = (float4*)(hT + j0C * XST + g0C);
                    hr[0] = make_float4(gelu(f0.x), gelu(f0.y), gelu(f1.x), gelu(f1.y));
                    hr[1] = make_float4(gelu(f2.x), gelu(f2.y), gelu(f3.x), gelu(f3.y));
                    f0 = unpk(a4); f1 = unpk(a5); f2 = unpk(a6); f3 = unpk(a7);
                    float4* hr2 = (float4*)(hT + (j0C + 1) * XST + g0C);
                    hr2[0] = make_float4(gelu(f0.x), gelu(f0.y), gelu(f1.x), gelu(f1.y));
                    hr2[1] = make_float4(gelu(f2.x), gelu(f2.y), gelu(f3.x), gelu(f3.y));
                }
            }
            __syncthreads();

            // ---- D: out = h@W2+b2; thread: (d,d+1)-pair x 4g, half-j
            {
                ull c0, c1, c2, c3;
                if (jhD) { c0 = c1 = c2 = c3 = 0ull; }
                else { c0 = c1 = c2 = c3 = bD; }
                const float* wp = w2s + jhD * 64 * 64 + d0D;
                const float* hp = hT + jhD * 64 * XST + g0D;
#pragma unroll 8
                for (int j = 0; j < 64; j++) {
                    ull wq = *(const ull*)(wp + j * 64);
                    float4 hv = *(const float4*)(hp + j * XST);
                    ffma2(c0, wq, dup2(hv.x)); ffma2(c1, wq, dup2(hv.y));
                    ffma2(c2, wq, dup2(hv.z)); ffma2(c3, wq, dup2(hv.w));
                }
                const int p512 = wl * 32 + lane;
                if (jhD) {
                    dP[0 * 512 + p512] = c0; dP[1 * 512 + p512] = c1;
                    dP[2 * 512 + p512] = c2; dP[3 * 512 + p512] = c3;
                }
                __syncthreads();
                if (!jhD) {
                    c0 = add2(c0, dP[0 * 512 + p512]); c1 = add2(c1, dP[1 * 512 + p512]);
                    c2 = add2(c2, dP[2 * 512 + p512]); c3 = add2(c3, dP[3 * 512 + p512]);
                    if (g0D + 0 < Gr) *(float2*)(out + outb[g0D + 0] + d0D) = unpk(c0);
                    if (g0D + 1 < Gr) *(float2*)(out + outb[g0D + 1] + d0D) = unpk(c1);
                    if (g0D + 2 < Gr) *(float2*)(out + outb[g0D + 2] + d0D) = unpk(c2);
                    if (g0D + 3 < Gr) *(float2*)(out + outb[g0D + 3] + d0D) = unpk(c3);
                }
            }
            __syncthreads();
        }
        // ---- grid barrier (128 CTAs, all resident at 1/SM)
        bar_target += 128;
        if (t == 0) {
            __threadfence();
            atomicAdd(&g_arrive, 1u);
            long long spins = 0;
            while (ldacq(&g_arrive) < bar_target) {
                if (++spins > (1ll << 20)) break;   // safety bail
                __nanosleep(32);
            }
        }
        __syncthreads();
    }
}

extern "C" void kernel_launch(void* const* d_in, const int* in_sizes, int n_in,
                              void* d_out, int out_size) {
    const float* root = (const float*)d_in[0];
    const float* W1   = (const float*)d_in[1];
    const float* b1   = (const float*)d_in[2];
    const float* W2   = (const float*)d_in[3];
    const float* b2   = (const float*)d_in[4];
    const int*   pidx = (const int*)d_in[5];
    const int*   typ  = (const int*)d_in[6];
    float* out = (float*)d_out;

    cudaFuncSetAttribute(k_depth, cudaFuncAttributeMaxDynamicSharedMemorySize, 32 * NN * 2);
    cudaFuncSetAttribute(k_main, cudaFuncAttributeMaxDynamicSharedMemorySize, SMEM_BYTES);

    k_init<<<256, 256>>>(root, out);
    k_depth<<<8, 32, 32 * NN * 2>>>(pidx);
    k_count<<<128, 256>>>(typ);
    k_merge<<<8, 1024>>>();
    k_scatter<<<128, 256>>>(typ);
    k_main<<<128, THREADS, SMEM_BYTES>>>(W1, b1, W2, b2, pidx, out);
}

// round 11
// speedup vs baseline: 1.3882x; 1.0567x over previous
#include <cuda_runtime.h>
#include <cstdint>
#include <cstddef>

#define NB 256
#define NN 2048
#define NR 64
#define ND 64
#define NT 8
#define G 64
#define THREADS 1024
#define TCAP 81920
#define XST 68               // xT/hT row stride in floats

typedef unsigned long long ull;

__device__ unsigned short g_lvl[NB * NN];
__device__ int g_maxlvl;
__device__ unsigned g_flag[NB * NN];
__device__ int g_cnt[128 * 1024];
__device__ int g_scat[128 * 1024];
__device__ int g_tlofs[NT * 1025];
__device__ int g_curn[NT * 1024];
__device__ int g_tasks[NT * TCAP];    // (b<<11)|pos, level-grouped per type

static __device__ __forceinline__ unsigned ldacq(const unsigned* p) {
    unsigned v; asm volatile("ld.acquire.gpu.u32 %0,[%1];" : "=r"(v) : "l"(p) : "memory"); return v;
}
static __device__ __forceinline__ void strel(unsigned* p, unsigned v) {
    asm volatile("st.release.gpu.u32 [%0],%1;" :: "l"(p), "r"(v) : "memory");
}
static __device__ __forceinline__ void ffma2(ull& d, ull a, ull b) {
    asm("fma.rn.f32x2 %0,%1,%2,%0;" : "+l"(d) : "l"(a), "l"(b));
}
static __device__ __forceinline__ ull add2(ull a, ull b) {
    ull r; asm("add.rn.f32x2 %0,%1,%2;" : "=l"(r) : "l"(a), "l"(b)); return r;
}
static __device__ __forceinline__ ull dup2(float x) {
    ull r; asm("mov.b64 %0,{%1,%1};" : "=l"(r) : "f"(x)); return r;
}
static __device__ __forceinline__ float2 unpk(ull v) {
    float2 f; asm("mov.b64 {%0,%1},%2;" : "=f"(f.x), "=f"(f.y) : "l"(v)); return f;
}
static __device__ __forceinline__ float gelu(float x) {
    return 0.5f * x * (1.0f + erff(x * 0.70710678118654752440f));
}

// -------- init: roots -> out, flags ----------------------------------------
__global__ void k_init(const float* __restrict__ root, float* __restrict__ out) {
    int tid = blockIdx.x * blockDim.x + threadIdx.x;
    int nt = gridDim.x * blockDim.x;
    if (tid == 0) g_maxlvl = 0;
    for (int i = tid; i < NB * NN; i += nt)
        g_flag[i] = ((i & (NN - 1)) < NR) ? 1u : 0u;
    const float4* r4 = (const float4*)root;
    float4* o4 = (float4*)out;
    const int RD4 = NR * ND / 4;
    for (int i = tid; i < NB * RD4; i += nt) {
        int b = i / RD4;
        o4[(size_t)b * (NN * ND / 4) + (i - b * RD4)] = r4[i];
    }
}

// -------- exact longest-path levels ----------------------------------------
__global__ void k_depth(const int* __restrict__ pidx) {
    extern __shared__ unsigned short slvl[];
    const int b = blockIdx.x * 32 + threadIdx.x;
    unsigned short* L = slvl + threadIdx.x * NN;
#pragma unroll
    for (int i = 0; i < NR; i++) L[i] = 0;
    const int2* pp = (const int2*)pidx + (size_t)b * NN;
    unsigned short* gl = g_lvl + (size_t)b * NN;
    int maxl = 0;
    for (int i = NR; i < NN; i += 2) {
        int4 q = *(const int4*)(pp + i);
        int l1 = L[q.x], l2 = L[q.y];
        int la = 1 + (l1 > l2 ? l1 : l2);
        L[i] = (unsigned short)la; gl[i] = (unsigned short)la;
        int l3 = L[q.z], l4 = L[q.w];
        int lb = 1 + (l3 > l4 ? l3 : l4);
        L[i + 1] = (unsigned short)lb; gl[i + 1] = (unsigned short)lb;
        int m = la > lb ? la : lb;
        if (m > maxl) maxl = m;
    }
    atomicMax(&g_maxlvl, maxl);
}

// -------- count / merge / scatter (per-type level queues) -------------------
__global__ void k_count(const int* __restrict__ types) {
    __shared__ int cnt[1024];
    const int c = blockIdx.x, ty = c >> 4, slot = c & 15, t = threadIdx.x;
    for (int l = t; l < 1024; l += 256) cnt[l] = 0;
    __syncthreads();
    for (int u = 0; u < 16; u++) {
        const int b = slot * 16 + u;
        for (int i = NR + t; i < NN; i += 256)
            if (types[b * NN + i] == ty)
                atomicAdd(&cnt[g_lvl[b * NN + i]], 1);
    }
    __syncthreads();
    for (int l = t; l < 1024; l += 256) g_cnt[c * 1024 + l] = cnt[l];
}

__global__ void k_merge() {
    __shared__ int sa[1024], sb_[1024];
    const int ty = blockIdx.x, l = threadIdx.x;
    int cs[16]; int tot = 0;
#pragma unroll
    for (int s = 0; s < 16; s++) { cs[s] = g_cnt[(ty * 16 + s) * 1024 + l]; tot += cs[s]; }
    sa[l] = tot;
    __syncthreads();
    int* pin = sa; int* pout = sb_;
    for (int off = 1; off < 1024; off <<= 1) {
        int v = pin[l] + (l >= off ? pin[l - off] : 0);
        pout[l] = v;
        __syncthreads();
        int* tmp = pin; pin = pout; pout = tmp;
    }
    int incl = pin[l];
    int excl = incl - tot;
    g_tlofs[ty * 1025 + l] = excl;
    if (l == 1023) g_tlofs[ty * 1025 + 1024] = incl;
    int run = excl;
#pragma unroll
    for (int s = 0; s < 16; s++) { g_scat[(ty * 16 + s) * 1024 + l] = run; run += cs[s]; }
    g_curn[ty * 1024 + l] = 0;
}

__global__ void k_scatter(const int* __restrict__ types) {
    __shared__ int wr[1024];
    const int c = blockIdx.x, ty = c >> 4, slot = c & 15, t = threadIdx.x;
    for (int l = t; l < 1024; l += 256) wr[l] = g_scat[c * 1024 + l];
    __syncthreads();
    for (int u = 0; u < 16; u++) {
        const int b = slot * 16 + u;
        for (int i = NR + t; i < NN; i += 256)
            if (types[b * NN + i] == ty) {
                int idx = atomicAdd(&wr[g_lvl[b * NN + i]], 1);
                if (idx < TCAP) g_tasks[ty * TCAP + idx] = (b << 11) | i;
            }
    }
}

// -------- main: async dataflow tiles, no grid barrier -----------------------
#define OFF_W2 16384
#define OFF_XT 24576                     // [i=128][XST]
#define OFF_HT (OFF_XT + 128 * XST)      // [j=128][XST]
#define OFF_HP (OFF_HT + 128 * XST)      // 4096 ull partials (C)
#define OFF_DP (OFF_HP + 8192)           // 2048 ull partials (D)
#define OFF_B1 (OFF_DP + 4096)
#define OFF_B2 (OFF_B1 + 128)
#define OFF_IS (OFF_B2 + 64)
#define SMEM_BYTES ((OFF_IS + 200) * 4)

__global__ void __launch_bounds__(THREADS, 1) k_main(
    const float* __restrict__ W1, const float* __restrict__ B1,
    const float* __restrict__ W2, const float* __restrict__ B2,
    const int* __restrict__ pidx, float* __restrict__ out)
{
    extern __shared__ float sm[];
    float* w1s = sm;                   // [i=128][j=128]
    float* w2s = sm + OFF_W2;          // [j=128][d=64]
    float* xT  = sm + OFF_XT;
    float* hT  = sm + OFF_HT;
    ull*   hP  = (ull*)(sm + OFF_HP);  // [acc=8][thr=512]
    ull*   dP  = (ull*)(sm + OFF_DP);  // [acc=4][thr=512]
    float* b1s = sm + OFF_B1;
    float* b2s = sm + OFF_B2;
    int* rowb  = (int*)(sm + OFF_IS);  // 128
    int* outb  = rowb + 128;           // 64
    int* sgrab = outb + 64;            // 1

    const int t = threadIdx.x, w = t >> 5, lane = t & 31;
    const int ty = blockIdx.x >> 4;

    {
        const float4* a = (const float4*)(W1 + ty * 16384);
        for (int i = t; i < 4096; i += THREADS) ((float4*)w1s)[i] = a[i];
        const float4* c2 = (const float4*)(W2 + ty * 8192);
        for (int i = t; i < 2048; i += THREADS) ((float4*)w2s)[i] = c2[i];
        if (t < 128) b1s[t] = B1[ty * 128 + t];
        if (t < 64) b2s[t] = B2[ty * 64 + t];
    }
    const int ml = g_maxlvl;
    const int* tlofs = g_tlofs + ty * 1025;
    const int* tasks = g_tasks + ty * TCAP;
    int* curs = g_curn + ty * 1024;
    __syncthreads();

    // role constants
    const int wl = w & 15;
    const int ihC = w >> 4;
    const int j0C = (wl >> 1) * 16 + (lane >> 2) * 2;
    const int g0C = (wl & 1) * 32 + (lane & 3) * 8;
    const float bC0 = b1s[j0C], bC1 = b1s[j0C + 1];
    const int jhD = w >> 4;
    const int d0D = (wl >> 2) * 16 + (lane >> 2) * 2;
    const int g0D = (wl & 3) * 16 + (lane & 3) * 4;
    const ull bD = *(const ull*)(b2s + d0D);
    const int dB = t & 63, rB = t >> 6;

    for (int l = 1; l <= ml; l++) {
        const int seg0 = tlofs[l], seg1 = tlofs[l + 1];
        for (;;) {
            if (t == 0) sgrab[0] = atomicAdd(&curs[l], G);
            __syncthreads();
            const int base = seg0 + sgrab[0];
            if (base >= seg1) break;
            const int Gr = min(G, seg1 - base);

            // ---- setup row bases (sentinel 0 -> root row, flag always 1)
            if (t < 2 * G) {
                int g = t >> 1, kk = t & 1;
                if (g < Gr) {
                    int task = tasks[base + g];
                    int pos = task & 2047, b = task >> 11;
                    int p = pidx[((size_t)b * NN + pos) * 2 + kk];
                    rowb[t] = (b * NN + p) * ND;
                    if (kk == 0) outb[g] = (b * NN + pos) * ND;
                } else {
                    rowb[t] = 0;
                    if (kk == 0) outb[g] = -1;
                }
            }
            __syncthreads();

            // ---- wait for all 128 parents (level-sorted -> usually instant)
            if (t < 128) {
                const unsigned* fp = &g_flag[((unsigned)rowb[t]) >> 6];
                long long it = 0;
                while (!ldacq(fp)) {
                    if (++it > (1ll << 22)) break;      // safety bail
                    if ((it & 15) == 15) __nanosleep(64);
                }
            }
            __syncthreads();

            // ---- gather: 128 parent rows -> xT[i][g]
#pragma unroll
            for (int e = 0; e < 8; e++) {
                int r = rB + 16 * e;            // 0..127
                int g = r >> 1, kk = r & 1;
                float v = 0.0f;
                if (g < Gr) v = out[rowb[r] + dB];
                xT[(kk * 64 + dB) * XST + g] = v;
            }
            __syncthreads();

            // ---- C: h = gelu(x@W1+b1); thread: 2j x 8g, half-i
            {
                ull a0, a1, a2, a3, a4, a5, a6, a7;
                if (ihC) { a0 = a1 = a2 = a3 = a4 = a5 = a6 = a7 = 0ull; }
                else {
                    a0 = a1 = a2 = a3 = dup2(bC0);
                    a4 = a5 = a6 = a7 = dup2(bC1);
                }
                const float* wp = w1s + ihC * 64 * 128 + j0C;
                const float* xp = xT + ihC * 64 * XST + g0C;
#pragma unroll 8
                for (int i = 0; i < 64; i++) {
                    float2 wv = *(const float2*)(wp + i * 128);
                    ulonglong2 x01 = *(const ulonglong2*)(xp + i * XST);
                    ulonglong2 x23 = *(const ulonglong2*)(xp + i * XST + 4);
                    ull wa = dup2(wv.x), wb = dup2(wv.y);
                    ffma2(a0, x01.x, wa); ffma2(a1, x01.y, wa);
                    ffma2(a2, x23.x, wa); ffma2(a3, x23.y, wa);
                    ffma2(a4, x01.x, wb); ffma2(a5, x01.y, wb);
                    ffma2(a6, x23.x, wb); ffma2(a7, x23.y, wb);
                }
                const int p512 = wl * 32 + lane;
                if (ihC) {
                    hP[0 * 512 + p512] = a0; hP[1 * 512 + p512] = a1;
                    hP[2 * 512 + p512] = a2; hP[3 * 512 + p512] = a3;
                    hP[4 * 512 + p512] = a4; hP[5 * 512 + p512] = a5;
                    hP[6 * 512 + p512] = a6; hP[7 * 512 + p512] = a7;
                }
                __syncthreads();
                if (!ihC) {
                    a0 = add2(a0, hP[0 * 512 + p512]); a1 = add2(a1, hP[1 * 512 + p512]);
                    a2 = add2(a2, hP[2 * 512 + p512]); a3 = add2(a3, hP[3 * 512 + p512]);
                    a4 = add2(a4, hP[4 * 512 + p512]); a5 = add2(a5, hP[5 * 512 + p512]);
                    a6 = add2(a6, hP[6 * 512 + p512]); a7 = add2(a7, hP[7 * 512 + p512]);
                    float2 f0 = unpk(a0), f1 = unpk(a1), f2 = unpk(a2), f3 = unpk(a3);
                    float4* hr = (float4*)(hT + j0C * XST + g0C);
                    hr[0] = make_float4(gelu(f0.x), gelu(f0.y), gelu(f1.x), gelu(f1.y));
                    hr[1] = make_float4(gelu(f2.x), gelu(f2.y), gelu(f3.x), gelu(f3.y));
                    f0 = unpk(a4); f1 = unpk(a5); f2 = unpk(a6); f3 = unpk(a7);
                    float4* hr2 = (float4*)(hT + (j0C + 1) * XST + g0C);
                    hr2[0] = make_float4(gelu(f0.x), gelu(f0.y), gelu(f1.x), gelu(f1.y));
                    hr2[1] = make_float4(gelu(f2.x), gelu(f2.y), gelu(f3.x), gelu(f3.y));
                }
            }
            __syncthreads();

            // ---- D: out = h@W2+b2; thread: (d,d+1)-pair x 4g, half-j
            {
                ull c0, c1, c2, c3;
                if (jhD) { c0 = c1 = c2 = c3 = 0ull; }
                else { c0 = c1 = c2 = c3 = bD; }
                const float* wp = w2s + jhD * 64 * 64 + d0D;
                const float* hp = hT + jhD * 64 * XST + g0D;
#pragma unroll 8
                for (int j = 0; j < 64; j++) {
                    ull wq = *(const ull*)(wp + j * 64);
                    float4 hv = *(const float4*)(hp + j * XST);
                    ffma2(c0, wq, dup2(hv.x)); ffma2(c1, wq, dup2(hv.y));
                    ffma2(c2, wq, dup2(hv.z)); ffma2(c3, wq, dup2(hv.w));
                }
                const int p512 = wl * 32 + lane;
                if (jhD) {
                    dP[0 * 512 + p512] = c0; dP[1 * 512 + p512] = c1;
                    dP[2 * 512 + p512] = c2; dP[3 * 512 + p512] = c3;
                }
                __syncthreads();
                if (!jhD) {
                    c0 = add2(c0, dP[0 * 512 + p512]); c1 = add2(c1, dP[1 * 512 + p512]);
                    c2 = add2(c2, dP[2 * 512 + p512]); c3 = add2(c3, dP[3 * 512 + p512]);
                    if (g0D + 0 < Gr) *(float2*)(out + outb[g0D + 0] + d0D) = unpk(c0);
                    if (g0D + 1 < Gr) *(float2*)(out + outb[g0D + 1] + d0D) = unpk(c1);
                    if (g0D + 2 < Gr) *(float2*)(out + outb[g0D + 2] + d0D) = unpk(c2);
                    if (g0D + 3 < Gr) *(float2*)(out + outb[g0D + 3] + d0D) = unpk(c3);
                }
            }
            __syncthreads();   // all row stores complete before publish

            // ---- publish: release flags for the 64 outputs
            if (t < Gr)
                strel(&g_flag[((unsigned)outb[t]) >> 6], 1u);
        }
    }
}

extern "C" void kernel_launch(void* const* d_in, const int* in_sizes, int n_in,
                              void* d_out, int out_size) {
    const float* root = (const float*)d_in[0];
    const float* W1   = (const float*)d_in[1];
    const float* b1   = (const float*)d_in[2];
    const float* W2   = (const float*)d_in[3];
    const float* b2   = (const float*)d_in[4];
    const int*   pidx = (const int*)d_in[5];
    const int*   typ  = (const int*)d_in[6];
    float* out = (float*)d_out;

    cudaFuncSetAttribute(k_depth, cudaFuncAttributeMaxDynamicSharedMemorySize, 32 * NN * 2);
    cudaFuncSetAttribute(k_main, cudaFuncAttributeMaxDynamicSharedMemorySize, SMEM_BYTES);

    k_init<<<256, 256>>>(root, out);
    k_depth<<<8, 32, 32 * NN * 2>>>(pidx);
    k_count<<<128, 256>>>(typ);
    k_merge<<<8, 1024>>>();
    k_scatter<<<128, 256>>>(typ);
    k_main<<<128, THREADS, SMEM_BYTES>>>(W1, b1, W2, b2, pidx, out);
}

// round 12
// speedup vs baseline: 1.5652x; 1.1274x over previous
#include <cuda_runtime.h>
#include <cstdint>
#include <cstddef>

#define NB 256
#define NN 2048
#define NR 64
#define ND 64
#define NT 8
#define G 64
#define THREADS 1024
#define TCAP 81920
#define XST 68

typedef unsigned long long ull;

__device__ unsigned short g_lvl[NB * NN];
__device__ int g_maxlvl;
__device__ unsigned g_flag[NB * NN];
__device__ int g_cnt[128 * 1024];
__device__ int g_scat[128 * 1024];
__device__ int g_tlofs[NT * 1025];
__device__ int g_curn[NT * 1024];
__device__ int g_tasks[NT * TCAP];

static __device__ __forceinline__ unsigned ldacq(const unsigned* p) {
    unsigned v; asm volatile("ld.acquire.gpu.u32 %0,[%1];" : "=r"(v) : "l"(p) : "memory"); return v;
}
static __device__ __forceinline__ void strel(unsigned* p, unsigned v) {
    asm volatile("st.release.gpu.u32 [%0],%1;" :: "l"(p), "r"(v) : "memory");
}
static __device__ __forceinline__ void ffma2(ull& d, ull a, ull b) {
    asm("fma.rn.f32x2 %0,%1,%2,%0;" : "+l"(d) : "l"(a), "l"(b));
}
static __device__ __forceinline__ ull add2(ull a, ull b) {
    ull r; asm("add.rn.f32x2 %0,%1,%2;" : "=l"(r) : "l"(a), "l"(b)); return r;
}
static __device__ __forceinline__ ull dup2(float x) {
    ull r; asm("mov.b64 %0,{%1,%1};" : "=l"(r) : "f"(x)); return r;
}
static __device__ __forceinline__ float2 unpk(ull v) {
    float2 f; asm("mov.b64 {%0,%1},%2;" : "=f"(f.x), "=f"(f.y) : "l"(v)); return f;
}
static __device__ __forceinline__ float gelu(float x) {
    return 0.5f * x * (1.0f + erff(x * 0.70710678118654752440f));
}

// -------- init -------------------------------------------------------------
__global__ void k_init(const float* __restrict__ root, float* __restrict__ out) {
    int tid = blockIdx.x * blockDim.x + threadIdx.x;
    int nt = gridDim.x * blockDim.x;
    if (tid == 0) g_maxlvl = 0;
    for (int i = tid; i < NB * NN; i += nt)
        g_flag[i] = ((i & (NN - 1)) < NR) ? 1u : 0u;
    const float4* r4 = (const float4*)root;
    float4* o4 = (float4*)out;
    const int RD4 = NR * ND / 4;
    for (int i = tid; i < NB * RD4; i += nt) {
        int b = i / RD4;
        o4[(size_t)b * (NN * ND / 4) + (i - b * RD4)] = r4[i];
    }
}

// -------- exact longest-path levels ----------------------------------------
__global__ void k_depth(const int* __restrict__ pidx) {
    extern __shared__ unsigned short slvl[];
    const int b = blockIdx.x * 32 + threadIdx.x;
    unsigned short* L = slvl + threadIdx.x * NN;
#pragma unroll
    for (int i = 0; i < NR; i++) L[i] = 0;
    const int2* pp = (const int2*)pidx + (size_t)b * NN;
    unsigned short* gl = g_lvl + (size_t)b * NN;
    int maxl = 0;
    for (int i = NR; i < NN; i += 2) {
        int4 q = *(const int4*)(pp + i);
        int l1 = L[q.x], l2 = L[q.y];
        int la = 1 + (l1 > l2 ? l1 : l2);
        L[i] = (unsigned short)la; gl[i] = (unsigned short)la;
        int l3 = L[q.z], l4 = L[q.w];
        int lb = 1 + (l3 > l4 ? l3 : l4);
        L[i + 1] = (unsigned short)lb; gl[i + 1] = (unsigned short)lb;
        int m = la > lb ? la : lb;
        if (m > maxl) maxl = m;
    }
    atomicMax(&g_maxlvl, maxl);
}

// -------- count / merge / scatter -------------------------------------------
__global__ void k_count(const int* __restrict__ types) {
    __shared__ int cnt[1024];
    const int c = blockIdx.x, ty = c >> 4, slot = c & 15, t = threadIdx.x;
    for (int l = t; l < 1024; l += 256) cnt[l] = 0;
    __syncthreads();
    for (int u = 0; u < 16; u++) {
        const int b = slot * 16 + u;
        for (int i = NR + t; i < NN; i += 256)
            if (types[b * NN + i] == ty)
                atomicAdd(&cnt[g_lvl[b * NN + i]], 1);
    }
    __syncthreads();
    for (int l = t; l < 1024; l += 256) g_cnt[c * 1024 + l] = cnt[l];
}

__global__ void k_merge() {
    __shared__ int sa[1024], sb_[1024];
    const int ty = blockIdx.x, l = threadIdx.x;
    int cs[16]; int tot = 0;
#pragma unroll
    for (int s = 0; s < 16; s++) { cs[s] = g_cnt[(ty * 16 + s) * 1024 + l]; tot += cs[s]; }
    sa[l] = tot;
    __syncthreads();
    int* pin = sa; int* pout = sb_;
    for (int off = 1; off < 1024; off <<= 1) {
        int v = pin[l] + (l >= off ? pin[l - off] : 0);
        pout[l] = v;
        __syncthreads();
        int* tmp = pin; pin = pout; pout = tmp;
    }
    int incl = pin[l];
    int excl = incl - tot;
    g_tlofs[ty * 1025 + l] = excl;
    if (l == 1023) g_tlofs[ty * 1025 + 1024] = incl;
    int run = excl;
#pragma unroll
    for (int s = 0; s < 16; s++) { g_scat[(ty * 16 + s) * 1024 + l] = run; run += cs[s]; }
    g_curn[ty * 1024 + l] = 0;
}

__global__ void k_scatter(const int* __restrict__ types) {
    __shared__ int wr[1024];
    const int c = blockIdx.x, ty = c >> 4, slot = c & 15, t = threadIdx.x;
    for (int l = t; l < 1024; l += 256) wr[l] = g_scat[c * 1024 + l];
    __syncthreads();
    for (int u = 0; u < 16; u++) {
        const int b = slot * 16 + u;
        for (int i = NR + t; i < NN; i += 256)
            if (types[b * NN + i] == ty) {
                int idx = atomicAdd(&wr[g_lvl[b * NN + i]], 1);
                if (idx < TCAP) g_tasks[ty * TCAP + idx] = (b << 11) | i;
            }
    }
}

// -------- main --------------------------------------------------------------
#define OFF_W2 16384
#define OFF_XT 24576
#define OFF_HT (OFF_XT + 128 * XST)     // 33280
#define OFF_SC (OFF_HT + 128 * XST)     // 41984 : scratch 6144 ull (48KB)
#define OFF_B1 (OFF_SC + 12288)         // 54272
#define OFF_B2 (OFF_B1 + 128)
#define OFF_IS (OFF_B2 + 64)
#define SMEM_BYTES ((OFF_IS + 256) * 4)

__global__ void __launch_bounds__(THREADS, 1) k_main(
    const float* __restrict__ W1, const float* __restrict__ B1,
    const float* __restrict__ W2, const float* __restrict__ B2,
    const int* __restrict__ pidx, float* __restrict__ out)
{
    extern __shared__ float sm[];
    float* w1s = sm;                   // [i=128][j=128]
    float* w2s = sm + OFF_W2;          // [j=128][d=64]
    float* xT  = sm + OFF_XT;          // [i=128][XST]
    float* hT  = sm + OFF_HT;          // [j=128][XST]
    ull*   scr = (ull*)(sm + OFF_SC);  // partials: C 16x256, D 16x384
    float* b1s = sm + OFF_B1;
    float* b2s = sm + OFF_B2;
    int* rowb  = (int*)(sm + OFF_IS);  // 128
    int* outb  = rowb + 128;           // 64
    int* sgrab = outb + 64;            // 1

    const int t = threadIdx.x, w = t >> 5, lane = t & 31;
    const int ty = blockIdx.x >> 4;

    {
        const float4* a = (const float4*)(W1 + ty * 16384);
        for (int i = t; i < 4096; i += THREADS) ((float4*)w1s)[i] = a[i];
        const float4* c2 = (const float4*)(W2 + ty * 8192);
        for (int i = t; i < 2048; i += THREADS) ((float4*)w2s)[i] = c2[i];
        if (t < 128) b1s[t] = B1[ty * 128 + t];
        if (t < 64) b2s[t] = B2[ty * 64 + t];
    }
    const int ml = g_maxlvl;
    const int* tlofs = g_tlofs + ty * 1025;
    const int* tasks = g_tasks + ty * TCAP;
    int* curs = g_curn + ty * 1024;
    __syncthreads();

    // C roles (warps 0..15): warp tile 32j x 32g, k-split 2, thread 4j x 8g
    const int jtC = w & 3, gtC = (w >> 2) & 1, ksC = w >> 3;
    const int j0C = jtC * 32 + (lane >> 2) * 4;
    const int g0C = gtC * 32 + (lane & 3) * 8;
    // D roles (warps 0..15): warp tile 32d x 32g, k-split 4, thread 4d x 8g
    const int d0D = (w & 1) * 32 + (lane >> 2) * 4;
    const int g0D = ((w >> 1) & 1) * 32 + (lane & 3) * 8;
    const int ksD = w >> 2;
    // gather roles
    const int dB = t & 63, rB = t >> 6;

    for (int l = 1; l <= ml; l++) {
        const int seg0 = tlofs[l], seg1 = tlofs[l + 1];
        for (;;) {
            if (t == 0) sgrab[0] = atomicAdd(&curs[l], G);
            __syncthreads();
            const int base = seg0 + sgrab[0];
            if (base >= seg1) break;
            const int Gr = min(G, seg1 - base);

            // ---- setup row bases (sentinel 0 -> root row of batch 0, flag=1)
            if (t < 2 * G) {
                int g = t >> 1, kk = t & 1;
                if (g < Gr) {
                    int task = tasks[base + g];
                    int pos = task & 2047, b = task >> 11;
                    int p = pidx[((size_t)b * NN + pos) * 2 + kk];
                    rowb[t] = (b * NN + p) * ND;
                    if (kk == 0) outb[g] = (b * NN + pos) * ND;
                } else {
                    rowb[t] = 0;
                    if (kk == 0) outb[g] = -1;
                }
            }
            __syncthreads();

            // ---- wait for parents
            if (t < 128) {
                const unsigned* fp = &g_flag[((unsigned)rowb[t]) >> 6];
                long long it = 0;
                while (!ldacq(fp)) {
                    if (++it > (1ll << 22)) break;
                    if ((it & 15) == 15) __nanosleep(64);
                }
            }
            __syncthreads();

            // ---- gather parent rows -> xT[i][g]
#pragma unroll
            for (int e = 0; e < 8; e++) {
                int r = rB + 16 * e;
                int g = r >> 1, kk = r & 1;
                float v = 0.0f;
                if (g < Gr) v = out[rowb[r] + dB];
                xT[(kk * 64 + dB) * XST + g] = v;
            }
            __syncthreads();

            ull acc[16];

            // ---- C: H = gelu(W1^T X + b1), warps 0..15
            if (w < 16) {
                if (ksC == 0) {
#pragma unroll
                    for (int q = 0; q < 4; q++) {
                        ull bv = dup2(b1s[j0C + q]);
                        acc[q * 4 + 0] = bv; acc[q * 4 + 1] = bv;
                        acc[q * 4 + 2] = bv; acc[q * 4 + 3] = bv;
                    }
                } else {
#pragma unroll
                    for (int a = 0; a < 16; a++) acc[a] = 0ull;
                }
                const float* wp = w1s + ksC * 64 * 128 + j0C;
                const float* xp = xT + ksC * 64 * XST + g0C;
#pragma unroll 2
                for (int i = 0; i < 64; i++) {
                    float4 wv = *(const float4*)(wp + i * 128);
                    ulonglong2 xa = *(const ulonglong2*)(xp + i * XST);
                    ulonglong2 xb = *(const ulonglong2*)(xp + i * XST + 4);
                    ull w0 = dup2(wv.x), w1 = dup2(wv.y), w2 = dup2(wv.z), w3 = dup2(wv.w);
                    ffma2(acc[0], xa.x, w0); ffma2(acc[1], xa.y, w0);
                    ffma2(acc[2], xb.x, w0); ffma2(acc[3], xb.y, w0);
                    ffma2(acc[4], xa.x, w1); ffma2(acc[5], xa.y, w1);
                    ffma2(acc[6], xb.x, w1); ffma2(acc[7], xb.y, w1);
                    ffma2(acc[8], xa.x, w2); ffma2(acc[9], xa.y, w2);
                    ffma2(acc[10], xb.x, w2); ffma2(acc[11], xb.y, w2);
                    ffma2(acc[12], xa.x, w3); ffma2(acc[13], xa.y, w3);
                    ffma2(acc[14], xb.x, w3); ffma2(acc[15], xb.y, w3);
                }
                if (ksC == 1) {
                    ull* cp = scr + (w - 8) * 32 + lane;
#pragma unroll
                    for (int a = 0; a < 16; a++) cp[a * 256] = acc[a];
                }
            }
            __syncthreads();
            // ---- C combine + GELU -> hT (warps 0..7)
            if (w < 8) {
                const ull* cp = scr + w * 32 + lane;
#pragma unroll
                for (int a = 0; a < 16; a++) acc[a] = add2(acc[a], cp[a * 256]);
#pragma unroll
                for (int q = 0; q < 4; q++) {
                    float2 f0 = unpk(acc[q * 4 + 0]), f1 = unpk(acc[q * 4 + 1]);
                    float2 f2 = unpk(acc[q * 4 + 2]), f3 = unpk(acc[q * 4 + 3]);
                    float4* hr = (float4*)(hT + (j0C + q) * XST + g0C);
                    hr[0] = make_float4(gelu(f0.x), gelu(f0.y), gelu(f1.x), gelu(f1.y));
                    hr[1] = make_float4(gelu(f2.x), gelu(f2.y), gelu(f3.x), gelu(f3.y));
                }
            }
            __syncthreads();

            // ---- D: O = W2^T H + b2, warps 0..15
            if (w < 16) {
                if (ksD == 0) {
#pragma unroll
                    for (int q = 0; q < 4; q++) {
                        ull bv = dup2(b2s[d0D + q]);
                        acc[q * 4 + 0] = bv; acc[q * 4 + 1] = bv;
                        acc[q * 4 + 2] = bv; acc[q * 4 + 3] = bv;
                    }
                } else {
#pragma unroll
                    for (int a = 0; a < 16; a++) acc[a] = 0ull;
                }
                const float* wp = w2s + ksD * 32 * 64 + d0D;
                const float* hp = hT + ksD * 32 * XST + g0D;
#pragma unroll 2
                for (int j = 0; j < 32; j++) {
                    float4 wv = *(const float4*)(wp + j * 64);
                    ulonglong2 ha = *(const ulonglong2*)(hp + j * XST);
                    ulonglong2 hb = *(const ulonglong2*)(hp + j * XST + 4);
                    ull w0 = dup2(wv.x), w1 = dup2(wv.y), w2 = dup2(wv.z), w3 = dup2(wv.w);
                    ffma2(acc[0], ha.x, w0); ffma2(acc[1], ha.y, w0);
                    ffma2(acc[2], hb.x, w0); ffma2(acc[3], hb.y, w0);
                    ffma2(acc[4], ha.x, w1); ffma2(acc[5], ha.y, w1);
                    ffma2(acc[6], hb.x, w1); ffma2(acc[7], hb.y, w1);
                    ffma2(acc[8], ha.x, w2); ffma2(acc[9], ha.y, w2);
                    ffma2(acc[10], hb.x, w2); ffma2(acc[11], hb.y, w2);
                    ffma2(acc[12], ha.x, w3); ffma2(acc[13], ha.y, w3);
                    ffma2(acc[14], hb.x, w3); ffma2(acc[15], hb.y, w3);
                }
                if (ksD >= 1) {
                    ull* dp = scr + (ksD - 1) * 128 + (w & 3) * 32 + lane;
#pragma unroll
                    for (int a = 0; a < 16; a++) dp[a * 384] = acc[a];
                }
            }
            __syncthreads();
            // ---- D combine + STG (warps 0..3)
            if (w < 4) {
                const ull* dp = scr + w * 32 + lane;
#pragma unroll
                for (int s = 0; s < 3; s++)
#pragma unroll
                    for (int a = 0; a < 16; a++)
                        acc[a] = add2(acc[a], dp[s * 128 + a * 384]);
                float od[4][8];
#pragma unroll
                for (int q = 0; q < 4; q++)
#pragma unroll
                    for (int p = 0; p < 4; p++) {
                        float2 f = unpk(acc[q * 4 + p]);
                        od[q][2 * p] = f.x; od[q][2 * p + 1] = f.y;
                    }
#pragma unroll
                for (int e = 0; e < 8; e++) {
                    int g = g0D + e;
                    if (g < Gr)
                        *(float4*)(out + outb[g] + d0D) =
                            make_float4(od[0][e], od[1][e], od[2][e], od[3][e]);
                }
            }
            __syncthreads();

            // ---- publish
            if (t < Gr)
                strel(&g_flag[((unsigned)outb[t]) >> 6], 1u);
        }
    }
}

extern "C" void kernel_launch(void* const* d_in, const int* in_sizes, int n_in,
                              void* d_out, int out_size) {
    const float* root = (const float*)d_in[0];
    const float* W1   = (const float*)d_in[1];
    const float* b1   = (const float*)d_in[2];
    const float* W2   = (const float*)d_in[3];
    const float* b2   = (const float*)d_in[4];
    const int*   pidx = (const int*)d_in[5];
    const int*   typ  = (const int*)d_in[6];
    float* out = (float*)d_out;

    cudaFuncSetAttribute(k_depth, cudaFuncAttributeMaxDynamicSharedMemorySize, 32 * NN * 2);
    cudaFuncSetAttribute(k_main, cudaFuncAttributeMaxDynamicSharedMemorySize, SMEM_BYTES);

    k_init<<<256, 256>>>(root, out);
    k_depth<<<8, 32, 32 * NN * 2>>>(pidx);
    k_count<<<128, 256>>>(typ);
    k_merge<<<8, 1024>>>();
    k_scatter<<<128, 256>>>(typ);
    k_main<<<128, THREADS, SMEM_BYTES>>>(W1, b1, W2, b2, pidx, out);
}